// round 5
// baseline (speedup 1.0000x reference)
#include <cuda_runtime.h>
#include <cuda_bf16.h>
#include <cstdint>
#include <math.h>

// ---------------- problem constants ----------------
#define HH   16        // H
#define HKV  8
#define DD   128       // D
#define TT   2048      // T
#define HID  2048
#define II   8192      // I
#define NREP 2
#define EPSF 1e-6f
#define SCALEF 0.08838834764831845f   // 1/sqrt(128)

// ---------------- scratch (device globals, no allocs) ----------------
__device__ float g_x  [TT * HID];
__device__ float g_h  [TT * HID];        // tf32-rounded
__device__ float g_q  [TT * HH  * DD];
__device__ float g_k  [TT * HKV * DD];
__device__ float g_v  [TT * HKV * DD];
__device__ float g_att[TT * HH  * DD];   // tf32-rounded
__device__ float g_hid[TT * HID];
__device__ float g_h2 [TT * HID];        // tf32-rounded
__device__ float g_gu [TT * 2 * II];
__device__ float g_act[TT * II];         // tf32-rounded
// tf32-converted weights (u32 bit patterns)
__device__ uint32_t g_wqkv_t[4096 * HID];   // rows: [0,2048)=wq [2048,3072)=wk [3072,4096)=wv
__device__ uint32_t g_wo_t  [HID * HH * DD];
__device__ uint32_t g_wgu_t [2 * II * HID];
__device__ uint32_t g_wd_t  [HID * II];

__device__ __forceinline__ uint32_t f2tf32(float f) {
    uint32_t o;
    asm("cvt.rna.tf32.f32 %0, %1;" : "=r"(o) : "f"(f));
    return o;
}

// ---------------- fp32 -> tf32 bit conversion ----------------
__global__ void cvt_tf32(const float4* __restrict__ src, uint4* __restrict__ dst, int n4) {
    int i = blockIdx.x * blockDim.x + threadIdx.x;
    if (i < n4) {
        float4 v = src[i];
        dst[i] = make_uint4(f2tf32(v.x), f2tf32(v.y), f2tf32(v.z), f2tf32(v.w));
    }
}

// ---------------- transpose: src[R][C] -> dst[C][R] ----------------
__global__ void transpose_k(const float* __restrict__ src, float* __restrict__ dst,
                            int R, int C) {
    __shared__ float tile[32][33];
    int r0 = blockIdx.y * 32, c0 = blockIdx.x * 32;
    int tx = threadIdx.x, ty = threadIdx.y;
    #pragma unroll
    for (int i = ty; i < 32; i += 8)
        tile[i][tx] = src[(size_t)(r0 + i) * C + c0 + tx];
    __syncthreads();
    #pragma unroll
    for (int i = ty; i < 32; i += 8)
        dst[(size_t)(c0 + i) * R + r0 + tx] = tile[tx][i];
}

// ---------------- row RMS norm (emits tf32-rounded values) ----------------
__global__ void rms_rows(const float* __restrict__ X, const float* __restrict__ w,
                         float* __restrict__ Y, int C) {
    int t = blockIdx.x;
    const float4* x4 = (const float4*)(X + (size_t)t * C);
    const float4* w4 = (const float4*)w;
    float4*       y4 = (float4*)(Y + (size_t)t * C);
    int n4 = C >> 2;
    float4 v[4];
    float ss = 0.f;
    int cnt = 0;
    for (int i = threadIdx.x; i < n4; i += 256) {
        float4 a = x4[i];
        v[cnt++] = a;
        ss += a.x * a.x + a.y * a.y + a.z * a.z + a.w * a.w;
    }
    #pragma unroll
    for (int o = 16; o; o >>= 1) ss += __shfl_xor_sync(0xffffffffu, ss, o);
    __shared__ float warpsum[8];
    if ((threadIdx.x & 31) == 0) warpsum[threadIdx.x >> 5] = ss;
    __syncthreads();
    ss = 0.f;
    #pragma unroll
    for (int i = 0; i < 8; i++) ss += warpsum[i];
    float r = rsqrtf(ss / (float)C + EPSF);
    cnt = 0;
    for (int i = threadIdx.x; i < n4; i += 256) {
        float4 a = v[cnt++];
        float4 ww = w4[i];
        float4 o;
        o.x = __uint_as_float(f2tf32(a.x * r * ww.x));
        o.y = __uint_as_float(f2tf32(a.y * r * ww.y));
        o.z = __uint_as_float(f2tf32(a.z * r * ww.z));
        o.w = __uint_as_float(f2tf32(a.w * r * ww.w));
        y4[i] = o;
    }
}

// ---------------- per-head RMS + RoPE (in place, fp32) ----------------
__global__ void qk_rms_rope(float* __restrict__ buf, const float* __restrict__ w,
                            const float* __restrict__ cosT, const float* __restrict__ sinT) {
    int h = blockIdx.x, t = blockIdx.y, nh = gridDim.x;
    float* row = buf + ((size_t)t * nh + h) * DD;
    int d = threadIdx.x;
    float v = row[d];
    float ss = v * v;
    #pragma unroll
    for (int o = 16; o; o >>= 1) ss += __shfl_xor_sync(0xffffffffu, ss, o);
    __shared__ float wsum[4];
    if ((d & 31) == 0) wsum[d >> 5] = ss;
    __syncthreads();
    ss = wsum[0] + wsum[1] + wsum[2] + wsum[3];
    float r = rsqrtf(ss / 128.f + EPSF);
    float qn = v * r * w[d];
    __shared__ float sh[128];
    sh[d] = qn;
    __syncthreads();
    float rot = (d < 64) ? -sh[d + 64] : sh[d - 64];
    row[d] = qn * cosT[(size_t)t * DD + d] + rot * sinT[(size_t)t * DD + d];
}

// ---------------- tf32 tensor-core GEMM, cp.async 4-stage, no in-loop cvt ----
// C[M,N] = A[M,K] * B[N,K]^T (+Res). A: tf32-rounded floats, B: tf32 u32.
// BM=128, BN in {128,256}, 256 thr, 8 warps (2m x 4n), warp tile 64 x BN/4.
#define GPITCH 36

#define MMA_TF32(d, a, b)                                                     \
    asm volatile("mma.sync.aligned.m16n8k8.row.col.f32.tf32.tf32.f32 "        \
                 "{%0,%1,%2,%3}, {%4,%5,%6,%7}, {%8,%9}, {%0,%1,%2,%3};"      \
                 : "+f"(d[0]), "+f"(d[1]), "+f"(d[2]), "+f"(d[3])             \
                 : "r"(a[0]), "r"(a[1]), "r"(a[2]), "r"(a[3]),                \
                   "r"(b[0]), "r"(b[1]))

template<int BN, bool QKV>
__global__ __launch_bounds__(256, 1) void gemm_tf32_ca(
    const float* __restrict__ A, const uint32_t* __restrict__ B,
    const float* __restrict__ Res, float* __restrict__ C,
    float* __restrict__ Ck, float* __restrict__ Cv,
    int N, int K) {
    constexpr int BM   = 128;
    constexpr int WN   = BN / 4;
    constexpr int NF   = WN / 8;
    extern __shared__ uint32_t smu[];
    uint32_t* SA = smu;                       // [4][BM][GPITCH]
    uint32_t* SB = smu + 4 * BM * GPITCH;     // [4][BN][GPITCH]

    const int bm = blockIdx.y * BM;
    const int bn = blockIdx.x * BN;
    const int tid = threadIdx.x;
    const int wid = tid >> 5, lane = tid & 31;
    const int wm = wid & 1, wn = wid >> 1;
    const int lr = lane >> 2, lc = lane & 3;
    const int nkt = K >> 5;

    auto issue = [&](int kt, int s) {
        int k0 = kt << 5;
        #pragma unroll
        for (int i = 0; i < BM / 32; i++) {
            int c = tid + i * 256;
            int r = c >> 3, c4 = (c & 7) << 2;
            const float* g = A + (size_t)(bm + r) * K + k0 + c4;
            uint32_t dst = (uint32_t)__cvta_generic_to_shared(
                &SA[(s * BM + r) * GPITCH + c4]);
            asm volatile("cp.async.cg.shared.global [%0], [%1], 16;\n"
                         :: "r"(dst), "l"(g));
        }
        #pragma unroll
        for (int i = 0; i < BN / 32; i++) {
            int c = tid + i * 256;
            int r = c >> 3, c4 = (c & 7) << 2;
            const uint32_t* g = B + (size_t)(bn + r) * K + k0 + c4;
            uint32_t dst = (uint32_t)__cvta_generic_to_shared(
                &SB[(s * BN + r) * GPITCH + c4]);
            asm volatile("cp.async.cg.shared.global [%0], [%1], 16;\n"
                         :: "r"(dst), "l"(g));
        }
        asm volatile("cp.async.commit_group;\n");
    };

    float acc[4][NF][4] = {};

    issue(0, 0);
    if (nkt > 1) issue(1, 1);
    if (nkt > 2) issue(2, 2);

    for (int kt = 0; kt < nkt; kt++) {
        int s = kt & 3;
        int rem = nkt - kt - 1;
        if (rem >= 2)      { asm volatile("cp.async.wait_group 2;\n"); }
        else if (rem == 1) { asm volatile("cp.async.wait_group 1;\n"); }
        else               { asm volatile("cp.async.wait_group 0;\n"); }
        __syncthreads();
        if (kt + 3 < nkt) issue(kt + 3, (kt + 3) & 3);

        const uint32_t* Ab = SA + (size_t)s * BM * GPITCH;
        const uint32_t* Bb = SB + (size_t)s * BN * GPITCH;
        #pragma unroll
        for (int ks = 0; ks < 32; ks += 8) {
            uint32_t af[4][4], bf[NF][2];
            #pragma unroll
            for (int mf = 0; mf < 4; mf++) {
                const uint32_t* p = Ab + (wm * 64 + mf * 16 + lr) * GPITCH + ks + lc;
                af[mf][0] = p[0];
                af[mf][1] = p[8 * GPITCH];
                af[mf][2] = p[4];
                af[mf][3] = p[8 * GPITCH + 4];
            }
            #pragma unroll
            for (int nf = 0; nf < NF; nf++) {
                const uint32_t* p = Bb + (wn * WN + nf * 8 + lr) * GPITCH + ks + lc;
                bf[nf][0] = p[0];
                bf[nf][1] = p[4];
            }
            #pragma unroll
            for (int mf = 0; mf < 4; mf++)
                #pragma unroll
                for (int nf = 0; nf < NF; nf++)
                    MMA_TF32(acc[mf][nf], af[mf], bf[nf]);
        }
    }

    // epilogue: pick output segment
    float* Cb;
    int Nloc, cl0;
    if (QKV) {
        if (bn < 2048)      { Cb = C;  Nloc = 2048; cl0 = bn; }
        else if (bn < 3072) { Cb = Ck; Nloc = 1024; cl0 = bn - 2048; }
        else                { Cb = Cv; Nloc = 1024; cl0 = bn - 3072; }
    } else {
        Cb = C; Nloc = N; cl0 = bn;
    }
    #pragma unroll
    for (int mf = 0; mf < 4; mf++) {
        #pragma unroll
        for (int nf = 0; nf < NF; nf++) {
            int rg = bm + wm * 64 + mf * 16 + lr;
            int cg = cl0 + wn * WN + nf * 8 + 2 * lc;
            float2 v0 = make_float2(acc[mf][nf][0], acc[mf][nf][1]);
            float2 v1 = make_float2(acc[mf][nf][2], acc[mf][nf][3]);
            if (!QKV && Res) {
                float2 r0 = *(const float2*)(Res + (size_t)rg * Nloc + cg);
                float2 r1 = *(const float2*)(Res + (size_t)(rg + 8) * Nloc + cg);
                v0.x += r0.x; v0.y += r0.y;
                v1.x += r1.x; v1.y += r1.y;
            }
            *(float2*)(Cb + (size_t)rg * Nloc + cg) = v0;
            *(float2*)(Cb + (size_t)(rg + 8) * Nloc + cg) = v1;
        }
    }
}

#define SMEM_G128 (4 * (128 + 128) * GPITCH * 4)   // 147456 B
#define SMEM_G256 (4 * (128 + 256) * GPITCH * 4)   // 221184 B

// ---------------- flash attention (fp32, causal, 64x64 tiles) ----------------
#define FLASH_SMEM ((64*128 + 128*68 + 64*68) * 4)
__global__ __launch_bounds__(256) void flash_attn(
    const float* __restrict__ Q, const float* __restrict__ Kg,
    const float* __restrict__ Vg, float* __restrict__ O) {
    extern __shared__ float sm[];
    float* Qs = sm;                 // [64][128]
    float* KT = Qs + 64 * 128;      // K as [128][68] ; reused as V [64][132]
    float* Ss = KT + 128 * 68;      // [64][68]
    __shared__ float m_s[64], l_s[64], al_s[64];

    int h  = blockIdx.y;
    int it = blockIdx.x;
    int i0 = it * 64;
    int hk = h >> 1;                // NREP = 2
    int tid = threadIdx.x, tx = tid & 15, ty = tid >> 4;

    for (int idx = tid; idx < 64 * 32; idx += 256) {
        int r = idx >> 5, d4 = (idx & 31) << 2;
        float4 v = *(const float4*)(Q + ((size_t)(i0 + r) * HH + h) * DD + d4);
        v.x *= SCALEF; v.y *= SCALEF; v.z *= SCALEF; v.w *= SCALEF;
        *(float4*)&Qs[r * 128 + d4] = v;
    }
    if (tid < 64) { m_s[tid] = -1e30f; l_s[tid] = 0.f; }

    float acc[4][8] = {};

    for (int kt = 0; kt <= it; kt++) {
        int j0 = kt * 64;
        __syncthreads();
        for (int idx = tid; idx < 64 * 32; idx += 256) {
            int c = idx >> 5, d4 = (idx & 31) << 2;
            float4 v = *(const float4*)(Kg + ((size_t)(j0 + c) * HKV + hk) * DD + d4);
            KT[(d4 + 0) * 68 + c] = v.x;
            KT[(d4 + 1) * 68 + c] = v.y;
            KT[(d4 + 2) * 68 + c] = v.z;
            KT[(d4 + 3) * 68 + c] = v.w;
        }
        __syncthreads();
        float s[4][4] = {};
        #pragma unroll 4
        for (int d = 0; d < 128; d++) {
            float4 kv = *(const float4*)&KT[d * 68 + tx * 4];
            float q0 = Qs[(ty * 4 + 0) * 128 + d];
            float q1 = Qs[(ty * 4 + 1) * 128 + d];
            float q2 = Qs[(ty * 4 + 2) * 128 + d];
            float q3 = Qs[(ty * 4 + 3) * 128 + d];
            s[0][0] += q0 * kv.x; s[0][1] += q0 * kv.y; s[0][2] += q0 * kv.z; s[0][3] += q0 * kv.w;
            s[1][0] += q1 * kv.x; s[1][1] += q1 * kv.y; s[1][2] += q1 * kv.z; s[1][3] += q1 * kv.w;
            s[2][0] += q2 * kv.x; s[2][1] += q2 * kv.y; s[2][2] += q2 * kv.z; s[2][3] += q2 * kv.w;
            s[3][0] += q3 * kv.x; s[3][1] += q3 * kv.y; s[3][2] += q3 * kv.z; s[3][3] += q3 * kv.w;
        }
        bool diag = (kt == it);
        #pragma unroll
        for (int i = 0; i < 4; i++)
            #pragma unroll
            for (int j = 0; j < 4; j++) {
                float vv = s[i][j];
                if (diag && (tx * 4 + j > ty * 4 + i)) vv = -1e30f;
                Ss[(ty * 4 + i) * 68 + tx * 4 + j] = vv;
            }
        __syncthreads();
        for (int idx = tid; idx < 64 * 32; idx += 256) {
            int c = idx >> 5, d4 = (idx & 31) << 2;
            float4 v = *(const float4*)(Vg + ((size_t)(j0 + c) * HKV + hk) * DD + d4);
            *(float4*)&KT[c * 132 + d4] = v;
        }
        if (tid < 64) {
            int r = tid;
            float mo = m_s[r];
            float mx = mo;
            #pragma unroll 8
            for (int c = 0; c < 64; c++) mx = fmaxf(mx, Ss[r * 68 + c]);
            float al = __expf(mo - mx);
            float sum = 0.f;
            #pragma unroll 8
            for (int c = 0; c < 64; c++) {
                float p = __expf(Ss[r * 68 + c] - mx);
                Ss[r * 68 + c] = p;
                sum += p;
            }
            m_s[r] = mx;
            al_s[r] = al;
            l_s[r] = l_s[r] * al + sum;
        }
        __syncthreads();
        #pragma unroll
        for (int i = 0; i < 4; i++) {
            float a = al_s[ty * 4 + i];
            #pragma unroll
            for (int j = 0; j < 8; j++) acc[i][j] *= a;
        }
        #pragma unroll 2
        for (int c = 0; c < 64; c++) {
            float p0 = Ss[(ty * 4 + 0) * 68 + c];
            float p1 = Ss[(ty * 4 + 1) * 68 + c];
            float p2 = Ss[(ty * 4 + 2) * 68 + c];
            float p3 = Ss[(ty * 4 + 3) * 68 + c];
            float4 v0 = *(const float4*)&KT[c * 132 + tx * 8];
            float4 v1 = *(const float4*)&KT[c * 132 + tx * 8 + 4];
            acc[0][0] += p0 * v0.x; acc[0][1] += p0 * v0.y; acc[0][2] += p0 * v0.z; acc[0][3] += p0 * v0.w;
            acc[0][4] += p0 * v1.x; acc[0][5] += p0 * v1.y; acc[0][6] += p0 * v1.z; acc[0][7] += p0 * v1.w;
            acc[1][0] += p1 * v0.x; acc[1][1] += p1 * v0.y; acc[1][2] += p1 * v0.z; acc[1][3] += p1 * v0.w;
            acc[1][4] += p1 * v1.x; acc[1][5] += p1 * v1.y; acc[1][6] += p1 * v1.z; acc[1][7] += p1 * v1.w;
            acc[2][0] += p2 * v0.x; acc[2][1] += p2 * v0.y; acc[2][2] += p2 * v0.z; acc[2][3] += p2 * v0.w;
            acc[2][4] += p2 * v1.x; acc[2][5] += p2 * v1.y; acc[2][6] += p2 * v1.z; acc[2][7] += p2 * v1.w;
            acc[3][0] += p3 * v0.x; acc[3][1] += p3 * v0.y; acc[3][2] += p3 * v0.z; acc[3][3] += p3 * v0.w;
            acc[3][4] += p3 * v1.x; acc[3][5] += p3 * v1.y; acc[3][6] += p3 * v1.z; acc[3][7] += p3 * v1.w;
        }
    }
    #pragma unroll
    for (int i = 0; i < 4; i++) {
        int r = ty * 4 + i;
        float inv = 1.f / l_s[r];
        float* op = O + ((size_t)(i0 + r) * HH + h) * DD + tx * 8;
        float4 o0, o1;
        o0.x = __uint_as_float(f2tf32(acc[i][0] * inv));
        o0.y = __uint_as_float(f2tf32(acc[i][1] * inv));
        o0.z = __uint_as_float(f2tf32(acc[i][2] * inv));
        o0.w = __uint_as_float(f2tf32(acc[i][3] * inv));
        o1.x = __uint_as_float(f2tf32(acc[i][4] * inv));
        o1.y = __uint_as_float(f2tf32(acc[i][5] * inv));
        o1.z = __uint_as_float(f2tf32(acc[i][6] * inv));
        o1.w = __uint_as_float(f2tf32(acc[i][7] * inv));
        *(float4*)(op)     = o0;
        *(float4*)(op + 4) = o1;
    }
}

// ---------------- silu(gate) * up (emits tf32-rounded) ----------------
__global__ void silu_mul(const float* __restrict__ gu, float* __restrict__ act) {
    int idx = blockIdx.x * blockDim.x + threadIdx.x;   // over T*I
    int t = idx >> 13;
    int i = idx & 8191;
    float g = gu[(size_t)t * (2 * II) + i];
    float u = gu[(size_t)t * (2 * II) + II + i];
    act[idx] = __uint_as_float(f2tf32(g / (1.f + __expf(-g)) * u));
}

// ---------------- launch ----------------
extern "C" void kernel_launch(void* const* d_in, const int* in_sizes, int n_in,
                              void* d_out, int out_size) {
    const float* hc    = (const float*)d_in[0];
    const float* cosT  = (const float*)d_in[1];
    const float* sinT  = (const float*)d_in[2];
    const float* wq    = (const float*)d_in[5];
    const float* wk    = (const float*)d_in[6];
    const float* wv    = (const float*)d_in[7];
    const float* wo    = (const float*)d_in[8];
    const float* wgu   = (const float*)d_in[9];
    const float* wd    = (const float*)d_in[10];
    const float* ilnw  = (const float*)d_in[11];
    const float* plnw  = (const float*)d_in[12];
    const float* qnw   = (const float*)d_in[13];
    const float* knw   = (const float*)d_in[14];
    float* out = (float*)d_out;

    float *px, *ph, *pq, *pk, *pv, *patt, *phid, *ph2, *pgu, *pact;
    uint32_t *pwqkv, *pwo, *pwgu, *pwd;
    cudaGetSymbolAddress((void**)&px,   g_x);
    cudaGetSymbolAddress((void**)&ph,   g_h);
    cudaGetSymbolAddress((void**)&pq,   g_q);
    cudaGetSymbolAddress((void**)&pk,   g_k);
    cudaGetSymbolAddress((void**)&pv,   g_v);
    cudaGetSymbolAddress((void**)&patt, g_att);
    cudaGetSymbolAddress((void**)&phid, g_hid);
    cudaGetSymbolAddress((void**)&ph2,  g_h2);
    cudaGetSymbolAddress((void**)&pgu,  g_gu);
    cudaGetSymbolAddress((void**)&pact, g_act);
    cudaGetSymbolAddress((void**)&pwqkv, g_wqkv_t);
    cudaGetSymbolAddress((void**)&pwo,   g_wo_t);
    cudaGetSymbolAddress((void**)&pwgu,  g_wgu_t);
    cudaGetSymbolAddress((void**)&pwd,   g_wd_t);

    cudaFuncSetAttribute(flash_attn, cudaFuncAttributeMaxDynamicSharedMemorySize, FLASH_SMEM);
    cudaFuncSetAttribute(gemm_tf32_ca<128, true>,  cudaFuncAttributeMaxDynamicSharedMemorySize, SMEM_G128);
    cudaFuncSetAttribute(gemm_tf32_ca<128, false>, cudaFuncAttributeMaxDynamicSharedMemorySize, SMEM_G128);
    cudaFuncSetAttribute(gemm_tf32_ca<256, false>, cudaFuncAttributeMaxDynamicSharedMemorySize, SMEM_G256);

    dim3 tb(32, 8);

    // 0. convert weights to tf32 (independent of activation chain)
    cvt_tf32<<<(2048 * 2048 / 4) / 256, 256>>>((const float4*)wq,  (uint4*)pwqkv, 2048 * 2048 / 4);
    cvt_tf32<<<(1024 * 2048 / 4) / 256, 256>>>((const float4*)wk,  (uint4*)(pwqkv + 2048 * 2048), 1024 * 2048 / 4);
    cvt_tf32<<<(1024 * 2048 / 4) / 256, 256>>>((const float4*)wv,  (uint4*)(pwqkv + 3072 * 2048), 1024 * 2048 / 4);
    cvt_tf32<<<(2048 * 2048 / 4) / 256, 256>>>((const float4*)wo,  (uint4*)pwo,  2048 * 2048 / 4);
    cvt_tf32<<<(16384 * 2048 / 4) / 256, 256>>>((const float4*)wgu, (uint4*)pwgu, 16384 * 2048 / 4);
    cvt_tf32<<<(2048 * 8192 / 4) / 256, 256>>>((const float4*)wd,  (uint4*)pwd,  2048 * 8192 / 4);

    // 1. x = hidden_conv^T   (hc is [HID][T])
    transpose_k<<<dim3(TT / 32, HID / 32), tb>>>(hc, px, HID, TT);
    // 2. h = rms(x) * input_ln_w   (tf32-rounded)
    rms_rows<<<TT, 256>>>(px, ilnw, ph, HID);
    // 3. fused QKV projection (512 CTAs)
    gemm_tf32_ca<128, true><<<dim3(32, 16), 256, SMEM_G128>>>(
        ph, pwqkv, nullptr, pq, pk, pv, 4096, HID);
    // 4. q/k head-RMS + rope (in place)
    qk_rms_rope<<<dim3(HH,  TT), 128>>>(pq, qnw, cosT, sinT);
    qk_rms_rope<<<dim3(HKV, TT), 128>>>(pk, knw, cosT, sinT);
    // 5. attention (emits tf32-rounded att)
    flash_attn<<<dim3(TT / 64, HH), 256, FLASH_SMEM>>>(pq, pk, pv, patt);
    // 6. hidden = x + att @ wo^T
    gemm_tf32_ca<128, false><<<dim3(16, 16), 256, SMEM_G128>>>(
        patt, pwo, px, phid, nullptr, nullptr, HID, HH * DD);
    // 7. h2 = rms(hidden) * post_ln_w  (tf32-rounded)
    rms_rows<<<TT, 256>>>(phid, plnw, ph2, HID);
    // 8. gate_up (1024 CTAs)
    gemm_tf32_ca<256, false><<<dim3(2 * II / 256, 16), 256, SMEM_G256>>>(
        ph2, pwgu, nullptr, pgu, nullptr, nullptr, 2 * II, HID);
    // 9. act = silu(gate) * up  (tf32-rounded)
    silu_mul<<<(TT * II) / 256, 256>>>(pgu, pact);
    // 10. hidden += act @ w_down^T
    gemm_tf32_ca<128, false><<<dim3(16, 16), 256, SMEM_G128>>>(
        pact, pwd, phid, phid, nullptr, nullptr, HID, II);
    // 11. out = hidden^T  ([T][HID] -> [HID][T])
    transpose_k<<<dim3(HID / 32, TT / 32), tb>>>(phid, out, TT, HID);
}

// round 6
// speedup vs baseline: 2.2215x; 2.2215x over previous
#include <cuda_runtime.h>
#include <cuda_bf16.h>
#include <cuda_fp16.h>
#include <cstdint>
#include <math.h>

// ---------------- problem constants ----------------
#define HH   16        // H
#define HKV  8
#define DD   128       // D
#define TT   2048      // T
#define HID  2048
#define II   8192      // I
#define NREP 2
#define EPSF 1e-6f
#define SCALEF 0.08838834764831845f   // 1/sqrt(128)

// ---------------- scratch (device globals, no allocs) ----------------
__device__ float g_x  [TT * HID];
__device__ float g_q  [TT * HH  * DD];
__device__ float g_k  [TT * HKV * DD];
__device__ float g_v  [TT * HKV * DD];
__device__ float g_hid[TT * HID];
__device__ float g_gu [TT * 2 * II];
// fp16 activation buffers
__device__ __align__(16) __half g_h_h  [TT * HID];
__device__ __align__(16) __half g_att_h[TT * HH * DD];
__device__ __align__(16) __half g_h2_h [TT * HID];
__device__ __align__(16) __half g_act_h[TT * II];
// fp16 weights (converted every replay)
__device__ __align__(16) __half g_wqkv_h[4096 * HID];
__device__ __align__(16) __half g_wo_h  [HID * HH * DD];
__device__ __align__(16) __half g_wgu_h [2 * II * HID];
__device__ __align__(16) __half g_wd_h  [HID * II];

// ---------------- fp32 -> fp16 conversion (8 floats / thread) ----------------
__global__ void cvt_f16(const float4* __restrict__ src, uint4* __restrict__ dst, int n8) {
    int i = blockIdx.x * blockDim.x + threadIdx.x;
    if (i < n8) {
        float4 a = src[2 * i], b = src[2 * i + 1];
        __half2 h0 = __floats2half2_rn(a.x, a.y);
        __half2 h1 = __floats2half2_rn(a.z, a.w);
        __half2 h2 = __floats2half2_rn(b.x, b.y);
        __half2 h3 = __floats2half2_rn(b.z, b.w);
        dst[i] = make_uint4(*(uint32_t*)&h0, *(uint32_t*)&h1,
                            *(uint32_t*)&h2, *(uint32_t*)&h3);
    }
}

// ---------------- transpose: src[R][C] -> dst[C][R] ----------------
__global__ void transpose_k(const float* __restrict__ src, float* __restrict__ dst,
                            int R, int C) {
    __shared__ float tile[32][33];
    int r0 = blockIdx.y * 32, c0 = blockIdx.x * 32;
    int tx = threadIdx.x, ty = threadIdx.y;
    #pragma unroll
    for (int i = ty; i < 32; i += 8)
        tile[i][tx] = src[(size_t)(r0 + i) * C + c0 + tx];
    __syncthreads();
    #pragma unroll
    for (int i = ty; i < 32; i += 8)
        dst[(size_t)(c0 + i) * R + r0 + tx] = tile[tx][i];
}

// ---------------- row RMS norm, fp16 output ----------------
__global__ void rms_rows_h(const float* __restrict__ X, const float* __restrict__ w,
                           __half* __restrict__ Y, int C) {
    int t = blockIdx.x;
    const float4* x4 = (const float4*)(X + (size_t)t * C);
    const float4* w4 = (const float4*)w;
    __half2*      y2 = (__half2*)(Y + (size_t)t * C);
    int n4 = C >> 2;
    float4 v[4];
    float ss = 0.f;
    int cnt = 0;
    for (int i = threadIdx.x; i < n4; i += 256) {
        float4 a = x4[i];
        v[cnt++] = a;
        ss += a.x * a.x + a.y * a.y + a.z * a.z + a.w * a.w;
    }
    #pragma unroll
    for (int o = 16; o; o >>= 1) ss += __shfl_xor_sync(0xffffffffu, ss, o);
    __shared__ float warpsum[8];
    if ((threadIdx.x & 31) == 0) warpsum[threadIdx.x >> 5] = ss;
    __syncthreads();
    ss = 0.f;
    #pragma unroll
    for (int i = 0; i < 8; i++) ss += warpsum[i];
    float r = rsqrtf(ss / (float)C + EPSF);
    cnt = 0;
    for (int i = threadIdx.x; i < n4; i += 256) {
        float4 a = v[cnt++];
        float4 ww = w4[i];
        y2[2 * i]     = __floats2half2_rn(a.x * r * ww.x, a.y * r * ww.y);
        y2[2 * i + 1] = __floats2half2_rn(a.z * r * ww.z, a.w * r * ww.w);
    }
}

// ---------------- per-head RMS + RoPE (in place, fp32) ----------------
__global__ void qk_rms_rope(float* __restrict__ buf, const float* __restrict__ w,
                            const float* __restrict__ cosT, const float* __restrict__ sinT) {
    int h = blockIdx.x, t = blockIdx.y, nh = gridDim.x;
    float* row = buf + ((size_t)t * nh + h) * DD;
    int d = threadIdx.x;
    float v = row[d];
    float ss = v * v;
    #pragma unroll
    for (int o = 16; o; o >>= 1) ss += __shfl_xor_sync(0xffffffffu, ss, o);
    __shared__ float wsum[4];
    if ((d & 31) == 0) wsum[d >> 5] = ss;
    __syncthreads();
    ss = wsum[0] + wsum[1] + wsum[2] + wsum[3];
    float r = rsqrtf(ss / 128.f + EPSF);
    float qn = v * r * w[d];
    __shared__ float sh[128];
    sh[d] = qn;
    __syncthreads();
    float rot = (d < 64) ? -sh[d + 64] : sh[d - 64];
    row[d] = qn * cosT[(size_t)t * DD + d] + rot * sinT[(size_t)t * DD + d];
}

// ---------------- fp16 tensor-core GEMM, cp.async 3-stage ----------------
// C[M,N] = A[M,K] * B[N,K]^T (+Res).  BM=BN=128, BK=32, 256 thr, 8 warps
// (2m x 4n), warp tile 64x32, mma m16n8k16 f16 with f32 accum.
#define HPITCH 40    // halfs per smem row (80 B, conflict-free: (20*lr+lc)%32 covers all banks)
#define SMEM_F16 (3 * (128 + 128) * HPITCH * 2)   // 61440 B

#define MMA_F16(d, a, b)                                                      \
    asm volatile("mma.sync.aligned.m16n8k16.row.col.f32.f16.f16.f32 "         \
                 "{%0,%1,%2,%3}, {%4,%5,%6,%7}, {%8,%9}, {%0,%1,%2,%3};"      \
                 : "+f"(d[0]), "+f"(d[1]), "+f"(d[2]), "+f"(d[3])             \
                 : "r"(a[0]), "r"(a[1]), "r"(a[2]), "r"(a[3]),                \
                   "r"(b[0]), "r"(b[1]))

template<bool QKV>
__global__ __launch_bounds__(256, 2) void gemm_f16(
    const __half* __restrict__ A, const __half* __restrict__ B,
    const float* __restrict__ Res, float* __restrict__ C,
    float* __restrict__ Ck, float* __restrict__ Cv,
    int N, int K) {
    constexpr int BM = 128, BN = 128;
    extern __shared__ __half shm[];
    __half* SA = shm;                     // [3][BM][HPITCH]
    __half* SB = shm + 3 * BM * HPITCH;   // [3][BN][HPITCH]

    const int bm = blockIdx.y * BM;
    const int bn = blockIdx.x * BN;
    const int tid = threadIdx.x;
    const int wid = tid >> 5, lane = tid & 31;
    const int wm = wid & 1, wn = wid >> 1;
    const int lr = lane >> 2, lc = lane & 3;
    const int nkt = K >> 5;

    auto issue = [&](int kt, int s) {
        int k0 = kt << 5;
        #pragma unroll
        for (int i = 0; i < 2; i++) {
            int cid = tid + i * 256;
            int r = cid >> 2, ch = cid & 3;          // 4 x 16B chunks per 64B row
            const __half* g = A + (size_t)(bm + r) * K + k0 + ch * 8;
            uint32_t dst = (uint32_t)__cvta_generic_to_shared(
                &SA[(s * BM + r) * HPITCH + ch * 8]);
            asm volatile("cp.async.cg.shared.global [%0], [%1], 16;\n"
                         :: "r"(dst), "l"(g));
        }
        #pragma unroll
        for (int i = 0; i < 2; i++) {
            int cid = tid + i * 256;
            int r = cid >> 2, ch = cid & 3;
            const __half* g = B + (size_t)(bn + r) * K + k0 + ch * 8;
            uint32_t dst = (uint32_t)__cvta_generic_to_shared(
                &SB[(s * BN + r) * HPITCH + ch * 8]);
            asm volatile("cp.async.cg.shared.global [%0], [%1], 16;\n"
                         :: "r"(dst), "l"(g));
        }
        asm volatile("cp.async.commit_group;\n");
    };

    float acc[4][4][4] = {};

    issue(0, 0);
    issue(1, 1);

    for (int kt = 0; kt < nkt; kt++) {
        int s = kt % 3;
        if (kt == nkt - 1) { asm volatile("cp.async.wait_group 0;\n"); }
        else               { asm volatile("cp.async.wait_group 1;\n"); }
        __syncthreads();
        if (kt + 2 < nkt) issue(kt + 2, (kt + 2) % 3);

        const __half* Ab = SA + s * BM * HPITCH;
        const __half* Bb = SB + s * BN * HPITCH;
        #pragma unroll
        for (int ks = 0; ks < 32; ks += 16) {
            uint32_t af[4][4], bf[4][2];
            #pragma unroll
            for (int mf = 0; mf < 4; mf++) {
                const __half* p = Ab + (wm * 64 + mf * 16 + lr) * HPITCH + ks + 2 * lc;
                af[mf][0] = *(const uint32_t*)(p);
                af[mf][1] = *(const uint32_t*)(p + 8 * HPITCH);
                af[mf][2] = *(const uint32_t*)(p + 8);
                af[mf][3] = *(const uint32_t*)(p + 8 * HPITCH + 8);
            }
            #pragma unroll
            for (int nf = 0; nf < 4; nf++) {
                const __half* p = Bb + (wn * 32 + nf * 8 + lr) * HPITCH + ks + 2 * lc;
                bf[nf][0] = *(const uint32_t*)(p);
                bf[nf][1] = *(const uint32_t*)(p + 8);
            }
            #pragma unroll
            for (int mf = 0; mf < 4; mf++)
                #pragma unroll
                for (int nf = 0; nf < 4; nf++)
                    MMA_F16(acc[mf][nf], af[mf], bf[nf]);
        }
    }

    // epilogue: pick output segment (QKV fused routing)
    float* Cb;
    int Nloc, cl0;
    if (QKV) {
        if (bn < 2048)      { Cb = C;  Nloc = 2048; cl0 = bn; }
        else if (bn < 3072) { Cb = Ck; Nloc = 1024; cl0 = bn - 2048; }
        else                { Cb = Cv; Nloc = 1024; cl0 = bn - 3072; }
    } else {
        Cb = C; Nloc = N; cl0 = bn;
    }
    #pragma unroll
    for (int mf = 0; mf < 4; mf++) {
        #pragma unroll
        for (int nf = 0; nf < 4; nf++) {
            int rg = bm + wm * 64 + mf * 16 + lr;
            int cg = cl0 + wn * 32 + nf * 8 + 2 * lc;
            float2 v0 = make_float2(acc[mf][nf][0], acc[mf][nf][1]);
            float2 v1 = make_float2(acc[mf][nf][2], acc[mf][nf][3]);
            if (!QKV && Res) {
                float2 r0 = *(const float2*)(Res + (size_t)rg * Nloc + cg);
                float2 r1 = *(const float2*)(Res + (size_t)(rg + 8) * Nloc + cg);
                v0.x += r0.x; v0.y += r0.y;
                v1.x += r1.x; v1.y += r1.y;
            }
            *(float2*)(Cb + (size_t)rg * Nloc + cg) = v0;
            *(float2*)(Cb + (size_t)(rg + 8) * Nloc + cg) = v1;
        }
    }
}

// ---------------- flash attention (fp32, causal, 64x64 tiles, fp16 out) ------
#define FLASH_SMEM ((64*128 + 128*68 + 64*68) * 4)
__global__ __launch_bounds__(256) void flash_attn(
    const float* __restrict__ Q, const float* __restrict__ Kg,
    const float* __restrict__ Vg, __half* __restrict__ O) {
    extern __shared__ float sm[];
    float* Qs = sm;                 // [64][128]
    float* KT = Qs + 64 * 128;      // K as [128][68] ; reused as V [64][132]
    float* Ss = KT + 128 * 68;      // [64][68]
    __shared__ float m_s[64], l_s[64], al_s[64];

    int h  = blockIdx.y;
    int it = blockIdx.x;
    int i0 = it * 64;
    int hk = h >> 1;                // NREP = 2
    int tid = threadIdx.x, tx = tid & 15, ty = tid >> 4;

    for (int idx = tid; idx < 64 * 32; idx += 256) {
        int r = idx >> 5, d4 = (idx & 31) << 2;
        float4 v = *(const float4*)(Q + ((size_t)(i0 + r) * HH + h) * DD + d4);
        v.x *= SCALEF; v.y *= SCALEF; v.z *= SCALEF; v.w *= SCALEF;
        *(float4*)&Qs[r * 128 + d4] = v;
    }
    if (tid < 64) { m_s[tid] = -1e30f; l_s[tid] = 0.f; }

    float acc[4][8] = {};

    for (int kt = 0; kt <= it; kt++) {
        int j0 = kt * 64;
        __syncthreads();
        for (int idx = tid; idx < 64 * 32; idx += 256) {
            int c = idx >> 5, d4 = (idx & 31) << 2;
            float4 v = *(const float4*)(Kg + ((size_t)(j0 + c) * HKV + hk) * DD + d4);
            KT[(d4 + 0) * 68 + c] = v.x;
            KT[(d4 + 1) * 68 + c] = v.y;
            KT[(d4 + 2) * 68 + c] = v.z;
            KT[(d4 + 3) * 68 + c] = v.w;
        }
        __syncthreads();
        float s[4][4] = {};
        #pragma unroll 4
        for (int d = 0; d < 128; d++) {
            float4 kv = *(const float4*)&KT[d * 68 + tx * 4];
            float q0 = Qs[(ty * 4 + 0) * 128 + d];
            float q1 = Qs[(ty * 4 + 1) * 128 + d];
            float q2 = Qs[(ty * 4 + 2) * 128 + d];
            float q3 = Qs[(ty * 4 + 3) * 128 + d];
            s[0][0] += q0 * kv.x; s[0][1] += q0 * kv.y; s[0][2] += q0 * kv.z; s[0][3] += q0 * kv.w;
            s[1][0] += q1 * kv.x; s[1][1] += q1 * kv.y; s[1][2] += q1 * kv.z; s[1][3] += q1 * kv.w;
            s[2][0] += q2 * kv.x; s[2][1] += q2 * kv.y; s[2][2] += q2 * kv.z; s[2][3] += q2 * kv.w;
            s[3][0] += q3 * kv.x; s[3][1] += q3 * kv.y; s[3][2] += q3 * kv.z; s[3][3] += q3 * kv.w;
        }
        bool diag = (kt == it);
        #pragma unroll
        for (int i = 0; i < 4; i++)
            #pragma unroll
            for (int j = 0; j < 4; j++) {
                float vv = s[i][j];
                if (diag && (tx * 4 + j > ty * 4 + i)) vv = -1e30f;
                Ss[(ty * 4 + i) * 68 + tx * 4 + j] = vv;
            }
        __syncthreads();
        for (int idx = tid; idx < 64 * 32; idx += 256) {
            int c = idx >> 5, d4 = (idx & 31) << 2;
            float4 v = *(const float4*)(Vg + ((size_t)(j0 + c) * HKV + hk) * DD + d4);
            *(float4*)&KT[c * 132 + d4] = v;
        }
        if (tid < 64) {
            int r = tid;
            float mo = m_s[r];
            float mx = mo;
            #pragma unroll 8
            for (int c = 0; c < 64; c++) mx = fmaxf(mx, Ss[r * 68 + c]);
            float al = __expf(mo - mx);
            float sum = 0.f;
            #pragma unroll 8
            for (int c = 0; c < 64; c++) {
                float p = __expf(Ss[r * 68 + c] - mx);
                Ss[r * 68 + c] = p;
                sum += p;
            }
            m_s[r] = mx;
            al_s[r] = al;
            l_s[r] = l_s[r] * al + sum;
        }
        __syncthreads();
        #pragma unroll
        for (int i = 0; i < 4; i++) {
            float a = al_s[ty * 4 + i];
            #pragma unroll
            for (int j = 0; j < 8; j++) acc[i][j] *= a;
        }
        #pragma unroll 2
        for (int c = 0; c < 64; c++) {
            float p0 = Ss[(ty * 4 + 0) * 68 + c];
            float p1 = Ss[(ty * 4 + 1) * 68 + c];
            float p2 = Ss[(ty * 4 + 2) * 68 + c];
            float p3 = Ss[(ty * 4 + 3) * 68 + c];
            float4 v0 = *(const float4*)&KT[c * 132 + tx * 8];
            float4 v1 = *(const float4*)&KT[c * 132 + tx * 8 + 4];
            acc[0][0] += p0 * v0.x; acc[0][1] += p0 * v0.y; acc[0][2] += p0 * v0.z; acc[0][3] += p0 * v0.w;
            acc[0][4] += p0 * v1.x; acc[0][5] += p0 * v1.y; acc[0][6] += p0 * v1.z; acc[0][7] += p0 * v1.w;
            acc[1][0] += p1 * v0.x; acc[1][1] += p1 * v0.y; acc[1][2] += p1 * v0.z; acc[1][3] += p1 * v0.w;
            acc[1][4] += p1 * v1.x; acc[1][5] += p1 * v1.y; acc[1][6] += p1 * v1.z; acc[1][7] += p1 * v1.w;
            acc[2][0] += p2 * v0.x; acc[2][1] += p2 * v0.y; acc[2][2] += p2 * v0.z; acc[2][3] += p2 * v0.w;
            acc[2][4] += p2 * v1.x; acc[2][5] += p2 * v1.y; acc[2][6] += p2 * v1.z; acc[2][7] += p2 * v1.w;
            acc[3][0] += p3 * v0.x; acc[3][1] += p3 * v0.y; acc[3][2] += p3 * v0.z; acc[3][3] += p3 * v0.w;
            acc[3][4] += p3 * v1.x; acc[3][5] += p3 * v1.y; acc[3][6] += p3 * v1.z; acc[3][7] += p3 * v1.w;
        }
    }
    #pragma unroll
    for (int i = 0; i < 4; i++) {
        int r = ty * 4 + i;
        float inv = 1.f / l_s[r];
        __half* op = O + ((size_t)(i0 + r) * HH + h) * DD + tx * 8;
        __half2 p0 = __floats2half2_rn(acc[i][0] * inv, acc[i][1] * inv);
        __half2 p1 = __floats2half2_rn(acc[i][2] * inv, acc[i][3] * inv);
        __half2 p2 = __floats2half2_rn(acc[i][4] * inv, acc[i][5] * inv);
        __half2 p3 = __floats2half2_rn(acc[i][6] * inv, acc[i][7] * inv);
        *(uint4*)op = make_uint4(*(uint32_t*)&p0, *(uint32_t*)&p1,
                                 *(uint32_t*)&p2, *(uint32_t*)&p3);
    }
}

// ---------------- silu(gate) * up, fp16 output ----------------
__global__ void silu_mul_h(const float* __restrict__ gu, __half* __restrict__ act) {
    int idx4 = blockIdx.x * blockDim.x + threadIdx.x;   // over T*I/4
    int e0 = idx4 << 2;
    int t = e0 >> 13;
    int i = e0 & 8191;
    float4 g = *(const float4*)(gu + (size_t)t * (2 * II) + i);
    float4 u = *(const float4*)(gu + (size_t)t * (2 * II) + II + i);
    float a0 = g.x / (1.f + __expf(-g.x)) * u.x;
    float a1 = g.y / (1.f + __expf(-g.y)) * u.y;
    float a2 = g.z / (1.f + __expf(-g.z)) * u.z;
    float a3 = g.w / (1.f + __expf(-g.w)) * u.w;
    __half2 h0 = __floats2half2_rn(a0, a1);
    __half2 h1 = __floats2half2_rn(a2, a3);
    *(uint2*)(act + (size_t)t * II + i) = make_uint2(*(uint32_t*)&h0, *(uint32_t*)&h1);
}

// ---------------- launch ----------------
extern "C" void kernel_launch(void* const* d_in, const int* in_sizes, int n_in,
                              void* d_out, int out_size) {
    const float* hc    = (const float*)d_in[0];
    const float* cosT  = (const float*)d_in[1];
    const float* sinT  = (const float*)d_in[2];
    const float* wq    = (const float*)d_in[5];
    const float* wk    = (const float*)d_in[6];
    const float* wv    = (const float*)d_in[7];
    const float* wo    = (const float*)d_in[8];
    const float* wgu   = (const float*)d_in[9];
    const float* wd    = (const float*)d_in[10];
    const float* ilnw  = (const float*)d_in[11];
    const float* plnw  = (const float*)d_in[12];
    const float* qnw   = (const float*)d_in[13];
    const float* knw   = (const float*)d_in[14];
    float* out = (float*)d_out;

    float *px, *pq, *pk, *pv, *phid, *pgu;
    __half *phh, *patth, *ph2h, *pacth, *pwqkv, *pwo, *pwgu, *pwd;
    cudaGetSymbolAddress((void**)&px,    g_x);
    cudaGetSymbolAddress((void**)&pq,    g_q);
    cudaGetSymbolAddress((void**)&pk,    g_k);
    cudaGetSymbolAddress((void**)&pv,    g_v);
    cudaGetSymbolAddress((void**)&phid,  g_hid);
    cudaGetSymbolAddress((void**)&pgu,   g_gu);
    cudaGetSymbolAddress((void**)&phh,   g_h_h);
    cudaGetSymbolAddress((void**)&patth, g_att_h);
    cudaGetSymbolAddress((void**)&ph2h,  g_h2_h);
    cudaGetSymbolAddress((void**)&pacth, g_act_h);
    cudaGetSymbolAddress((void**)&pwqkv, g_wqkv_h);
    cudaGetSymbolAddress((void**)&pwo,   g_wo_h);
    cudaGetSymbolAddress((void**)&pwgu,  g_wgu_h);
    cudaGetSymbolAddress((void**)&pwd,   g_wd_h);

    cudaFuncSetAttribute(flash_attn, cudaFuncAttributeMaxDynamicSharedMemorySize, FLASH_SMEM);
    cudaFuncSetAttribute(gemm_f16<true>,  cudaFuncAttributeMaxDynamicSharedMemorySize, SMEM_F16);
    cudaFuncSetAttribute(gemm_f16<false>, cudaFuncAttributeMaxDynamicSharedMemorySize, SMEM_F16);

    dim3 tb(32, 8);

    // 0. convert weights to fp16 (per replay, ~120 us total)
    cvt_f16<<<(2048 * 2048 / 8) / 256, 256>>>((const float4*)wq,  (uint4*)pwqkv, 2048 * 2048 / 8);
    cvt_f16<<<(1024 * 2048 / 8) / 256, 256>>>((const float4*)wk,  (uint4*)(pwqkv + 2048 * 2048), 1024 * 2048 / 8);
    cvt_f16<<<(1024 * 2048 / 8) / 256, 256>>>((const float4*)wv,  (uint4*)(pwqkv + 3072 * 2048), 1024 * 2048 / 8);
    cvt_f16<<<(2048 * 2048 / 8) / 256, 256>>>((const float4*)wo,  (uint4*)pwo,  2048 * 2048 / 8);
    cvt_f16<<<(16384 * 2048 / 8) / 256, 256>>>((const float4*)wgu, (uint4*)pwgu, 16384 * 2048 / 8);
    cvt_f16<<<(2048 * 8192 / 8) / 256, 256>>>((const float4*)wd,  (uint4*)pwd,  2048 * 8192 / 8);

    // 1. x = hidden_conv^T   (hc is [HID][T])
    transpose_k<<<dim3(TT / 32, HID / 32), tb>>>(hc, px, HID, TT);
    // 2. h = rms(x) * input_ln_w  -> fp16
    rms_rows_h<<<TT, 256>>>(px, ilnw, phh, HID);
    // 3. fused QKV projection (512 CTAs, fp16 tensor cores)
    gemm_f16<true><<<dim3(32, 16), 256, SMEM_F16>>>(
        phh, pwqkv, nullptr, pq, pk, pv, 4096, HID);
    // 4. q/k head-RMS + rope (in place, fp32)
    qk_rms_rope<<<dim3(HH,  TT), 128>>>(pq, qnw, cosT, sinT);
    qk_rms_rope<<<dim3(HKV, TT), 128>>>(pk, knw, cosT, sinT);
    // 5. attention (fp32 math, fp16 output)
    flash_attn<<<dim3(TT / 64, HH), 256, FLASH_SMEM>>>(pq, pk, pv, patth);
    // 6. hidden = x + att @ wo^T
    gemm_f16<false><<<dim3(16, 16), 256, SMEM_F16>>>(
        patth, pwo, px, phid, nullptr, nullptr, HID, HH * DD);
    // 7. h2 = rms(hidden) * post_ln_w -> fp16
    rms_rows_h<<<TT, 256>>>(phid, plnw, ph2h, HID);
    // 8. gate_up (2048 CTAs)
    gemm_f16<false><<<dim3(128, 16), 256, SMEM_F16>>>(
        ph2h, pwgu, nullptr, pgu, nullptr, nullptr, 2 * II, HID);
    // 9. act = silu(gate) * up -> fp16
    silu_mul_h<<<(TT * II / 4) / 256, 256>>>(pgu, pacth);
    // 10. hidden += act @ w_down^T
    gemm_f16<false><<<dim3(16, 16), 256, SMEM_F16>>>(
        pacth, pwd, phid, phid, nullptr, nullptr, HID, II);
    // 11. out = hidden^T  ([T][HID] -> [HID][T])
    transpose_k<<<dim3(HID / 32, TT / 32), tb>>>(phid, out, TT, HID);
}

// round 7
// speedup vs baseline: 2.3686x; 1.0662x over previous
#include <cuda_runtime.h>
#include <cuda_bf16.h>
#include <cuda_fp16.h>
#include <cstdint>
#include <math.h>

// ---------------- problem constants ----------------
#define HH   16        // H
#define HKV  8
#define DD   128       // D
#define TT   2048      // T
#define HID  2048
#define II   8192      // I
#define NREP 2
#define EPSF 1e-6f
#define SCALEF 0.08838834764831845f   // 1/sqrt(128)

// ---------------- scratch (device globals, no allocs) ----------------
__device__ float g_x  [TT * HID];
__device__ float g_q  [TT * HH  * DD];
__device__ float g_k  [TT * HKV * DD];
__device__ float g_v  [TT * HKV * DD];
__device__ float g_hid[TT * HID];
__device__ float g_gu [TT * 2 * II];
// fp16 activation buffers
__device__ __align__(16) __half g_h_h  [TT * HID];
__device__ __align__(16) __half g_att_h[TT * HH * DD];
__device__ __align__(16) __half g_h2_h [TT * HID];
__device__ __align__(16) __half g_act_h[TT * II];
__device__ __align__(16) __half g_q_h  [TT * HH * DD];
__device__ __align__(16) __half g_k_h  [TT * HKV * DD];
__device__ __align__(16) __half g_vt_h [HKV * DD * TT];   // [hk][d][t]
// fp16 weights (converted every replay)
__device__ __align__(16) __half g_wqkv_h[4096 * HID];
__device__ __align__(16) __half g_wo_h  [HID * HH * DD];
__device__ __align__(16) __half g_wgu_h [2 * II * HID];
__device__ __align__(16) __half g_wd_h  [HID * II];

// ---------------- fp32 -> fp16 conversion (8 floats / thread) ----------------
__global__ void cvt_f16(const float4* __restrict__ src, uint4* __restrict__ dst, int n8) {
    int i = blockIdx.x * blockDim.x + threadIdx.x;
    if (i < n8) {
        float4 a = src[2 * i], b = src[2 * i + 1];
        __half2 h0 = __floats2half2_rn(a.x, a.y);
        __half2 h1 = __floats2half2_rn(a.z, a.w);
        __half2 h2 = __floats2half2_rn(b.x, b.y);
        __half2 h3 = __floats2half2_rn(b.z, b.w);
        dst[i] = make_uint4(*(uint32_t*)&h0, *(uint32_t*)&h1,
                            *(uint32_t*)&h2, *(uint32_t*)&h3);
    }
}

// ---------------- transpose: src[R][C] -> dst[C][R] ----------------
__global__ void transpose_k(const float* __restrict__ src, float* __restrict__ dst,
                            int R, int C) {
    __shared__ float tile[32][33];
    int r0 = blockIdx.y * 32, c0 = blockIdx.x * 32;
    int tx = threadIdx.x, ty = threadIdx.y;
    #pragma unroll
    for (int i = ty; i < 32; i += 8)
        tile[i][tx] = src[(size_t)(r0 + i) * C + c0 + tx];
    __syncthreads();
    #pragma unroll
    for (int i = ty; i < 32; i += 8)
        dst[(size_t)(c0 + i) * R + r0 + tx] = tile[tx][i];
}

// ---------------- V transpose+convert: [T][HKV][D] f32 -> [hk][d][t] f16 -----
__global__ void v_trans_h(const float* __restrict__ V, __half* __restrict__ VT) {
    __shared__ __half tile[32][33];
    int t0 = blockIdx.x * 32, d0 = blockIdx.y * 32, hk = blockIdx.z;
    int tx = threadIdx.x, ty = threadIdx.y;
    #pragma unroll
    for (int i = ty; i < 32; i += 8)
        tile[i][tx] = __float2half(V[((size_t)(t0 + i) * HKV + hk) * DD + d0 + tx]);
    __syncthreads();
    #pragma unroll
    for (int i = ty; i < 32; i += 8)
        VT[((size_t)hk * DD + d0 + i) * TT + t0 + tx] = tile[tx][i];
}

// ---------------- row RMS norm, fp16 output ----------------
__global__ void rms_rows_h(const float* __restrict__ X, const float* __restrict__ w,
                           __half* __restrict__ Y, int C) {
    int t = blockIdx.x;
    const float4* x4 = (const float4*)(X + (size_t)t * C);
    const float4* w4 = (const float4*)w;
    __half2*      y2 = (__half2*)(Y + (size_t)t * C);
    int n4 = C >> 2;
    float4 v[4];
    float ss = 0.f;
    int cnt = 0;
    for (int i = threadIdx.x; i < n4; i += 256) {
        float4 a = x4[i];
        v[cnt++] = a;
        ss += a.x * a.x + a.y * a.y + a.z * a.z + a.w * a.w;
    }
    #pragma unroll
    for (int o = 16; o; o >>= 1) ss += __shfl_xor_sync(0xffffffffu, ss, o);
    __shared__ float warpsum[8];
    if ((threadIdx.x & 31) == 0) warpsum[threadIdx.x >> 5] = ss;
    __syncthreads();
    ss = 0.f;
    #pragma unroll
    for (int i = 0; i < 8; i++) ss += warpsum[i];
    float r = rsqrtf(ss / (float)C + EPSF);
    cnt = 0;
    for (int i = threadIdx.x; i < n4; i += 256) {
        float4 a = v[cnt++];
        float4 ww = w4[i];
        y2[2 * i]     = __floats2half2_rn(a.x * r * ww.x, a.y * r * ww.y);
        y2[2 * i + 1] = __floats2half2_rn(a.z * r * ww.z, a.w * r * ww.w);
    }
}

// ---------------- per-head RMS + RoPE -> fp16 (optionally pre-scaled) --------
__global__ void qk_rms_rope_h(const float* __restrict__ buf, const float* __restrict__ w,
                              const float* __restrict__ cosT, const float* __restrict__ sinT,
                              __half* __restrict__ outp, float scale) {
    int h = blockIdx.x, t = blockIdx.y, nh = gridDim.x;
    const float* row = buf + ((size_t)t * nh + h) * DD;
    int d = threadIdx.x;
    float v = row[d];
    float ss = v * v;
    #pragma unroll
    for (int o = 16; o; o >>= 1) ss += __shfl_xor_sync(0xffffffffu, ss, o);
    __shared__ float wsum[4];
    if ((d & 31) == 0) wsum[d >> 5] = ss;
    __syncthreads();
    ss = wsum[0] + wsum[1] + wsum[2] + wsum[3];
    float r = rsqrtf(ss / 128.f + EPSF);
    float qn = v * r * w[d];
    __shared__ float sh[128];
    sh[d] = qn;
    __syncthreads();
    float rot = (d < 64) ? -sh[d + 64] : sh[d - 64];
    float val = (qn * cosT[(size_t)t * DD + d] + rot * sinT[(size_t)t * DD + d]) * scale;
    outp[((size_t)t * nh + h) * DD + d] = __float2half(val);
}

#define MMA_F16(d, a, b)                                                      \
    asm volatile("mma.sync.aligned.m16n8k16.row.col.f32.f16.f16.f32 "         \
                 "{%0,%1,%2,%3}, {%4,%5,%6,%7}, {%8,%9}, {%0,%1,%2,%3};"      \
                 : "+f"(d[0]), "+f"(d[1]), "+f"(d[2]), "+f"(d[3])             \
                 : "r"(a[0]), "r"(a[1]), "r"(a[2]), "r"(a[3]),                \
                   "r"(b[0]), "r"(b[1]))

// ---------------- fp16 tensor-core GEMM, cp.async 3-stage ----------------
#define HPITCH 40    // halfs per smem row (80 B): bank (20*lr+lc)%32 all-distinct
#define SMEM_F16 (3 * (128 + 128) * HPITCH * 2)   // 61440 B

template<bool QKV>
__global__ __launch_bounds__(256, 2) void gemm_f16(
    const __half* __restrict__ A, const __half* __restrict__ B,
    const float* __restrict__ Res, float* __restrict__ C,
    float* __restrict__ Ck, float* __restrict__ Cv,
    int N, int K) {
    constexpr int BM = 128, BN = 128;
    extern __shared__ __half shm[];
    __half* SA = shm;                     // [3][BM][HPITCH]
    __half* SB = shm + 3 * BM * HPITCH;   // [3][BN][HPITCH]

    const int bm = blockIdx.y * BM;
    const int bn = blockIdx.x * BN;
    const int tid = threadIdx.x;
    const int wid = tid >> 5, lane = tid & 31;
    const int wm = wid & 1, wn = wid >> 1;
    const int lr = lane >> 2, lc = lane & 3;
    const int nkt = K >> 5;

    auto issue = [&](int kt, int s) {
        int k0 = kt << 5;
        #pragma unroll
        for (int i = 0; i < 2; i++) {
            int cid = tid + i * 256;
            int r = cid >> 2, ch = cid & 3;
            const __half* g = A + (size_t)(bm + r) * K + k0 + ch * 8;
            uint32_t dst = (uint32_t)__cvta_generic_to_shared(
                &SA[(s * BM + r) * HPITCH + ch * 8]);
            asm volatile("cp.async.cg.shared.global [%0], [%1], 16;\n"
                         :: "r"(dst), "l"(g));
        }
        #pragma unroll
        for (int i = 0; i < 2; i++) {
            int cid = tid + i * 256;
            int r = cid >> 2, ch = cid & 3;
            const __half* g = B + (size_t)(bn + r) * K + k0 + ch * 8;
            uint32_t dst = (uint32_t)__cvta_generic_to_shared(
                &SB[(s * BN + r) * HPITCH + ch * 8]);
            asm volatile("cp.async.cg.shared.global [%0], [%1], 16;\n"
                         :: "r"(dst), "l"(g));
        }
        asm volatile("cp.async.commit_group;\n");
    };

    float acc[4][4][4] = {};

    issue(0, 0);
    issue(1, 1);

    for (int kt = 0; kt < nkt; kt++) {
        int s = kt % 3;
        if (kt == nkt - 1) { asm volatile("cp.async.wait_group 0;\n"); }
        else               { asm volatile("cp.async.wait_group 1;\n"); }
        __syncthreads();
        if (kt + 2 < nkt) issue(kt + 2, (kt + 2) % 3);

        const __half* Ab = SA + s * BM * HPITCH;
        const __half* Bb = SB + s * BN * HPITCH;
        #pragma unroll
        for (int ks = 0; ks < 32; ks += 16) {
            uint32_t af[4][4], bf[4][2];
            #pragma unroll
            for (int mf = 0; mf < 4; mf++) {
                const __half* p = Ab + (wm * 64 + mf * 16 + lr) * HPITCH + ks + 2 * lc;
                af[mf][0] = *(const uint32_t*)(p);
                af[mf][1] = *(const uint32_t*)(p + 8 * HPITCH);
                af[mf][2] = *(const uint32_t*)(p + 8);
                af[mf][3] = *(const uint32_t*)(p + 8 * HPITCH + 8);
            }
            #pragma unroll
            for (int nf = 0; nf < 4; nf++) {
                const __half* p = Bb + (wn * 32 + nf * 8 + lr) * HPITCH + ks + 2 * lc;
                bf[nf][0] = *(const uint32_t*)(p);
                bf[nf][1] = *(const uint32_t*)(p + 8);
            }
            #pragma unroll
            for (int mf = 0; mf < 4; mf++)
                #pragma unroll
                for (int nf = 0; nf < 4; nf++)
                    MMA_F16(acc[mf][nf], af[mf], bf[nf]);
        }
    }

    float* Cb;
    int Nloc, cl0;
    if (QKV) {
        if (bn < 2048)      { Cb = C;  Nloc = 2048; cl0 = bn; }
        else if (bn < 3072) { Cb = Ck; Nloc = 1024; cl0 = bn - 2048; }
        else                { Cb = Cv; Nloc = 1024; cl0 = bn - 3072; }
    } else {
        Cb = C; Nloc = N; cl0 = bn;
    }
    #pragma unroll
    for (int mf = 0; mf < 4; mf++) {
        #pragma unroll
        for (int nf = 0; nf < 4; nf++) {
            int rg = bm + wm * 64 + mf * 16 + lr;
            int cg = cl0 + wn * 32 + nf * 8 + 2 * lc;
            float2 v0 = make_float2(acc[mf][nf][0], acc[mf][nf][1]);
            float2 v1 = make_float2(acc[mf][nf][2], acc[mf][nf][3]);
            if (!QKV && Res) {
                float2 r0 = *(const float2*)(Res + (size_t)rg * Nloc + cg);
                float2 r1 = *(const float2*)(Res + (size_t)(rg + 8) * Nloc + cg);
                v0.x += r0.x; v0.y += r0.y;
                v1.x += r1.x; v1.y += r1.y;
            }
            *(float2*)(Cb + (size_t)rg * Nloc + cg) = v0;
            *(float2*)(Cb + (size_t)(rg + 8) * Nloc + cg) = v1;
        }
    }
}

// ---------------- tensor-core flash attention ----------------
// CTA: 128 q rows x 1 head; 8 warps, warp = m16. S,PV via mma m16n8k16.
#define ATT_QP 136
#define ATT_KP 136
#define ATT_VP 72
#define ATT_SMEM ((128 * ATT_QP + 64 * ATT_KP + 128 * ATT_VP) * 2)  // 70656 B

__global__ __launch_bounds__(256, 1) void flash_attn_h(
    const __half* __restrict__ Qh, const __half* __restrict__ Kh,
    const __half* __restrict__ VTh, __half* __restrict__ O) {
    extern __shared__ __half sma[];
    __half* Qs  = sma;                    // [128][136]
    __half* Ks  = Qs + 128 * ATT_QP;      // [64][136]
    __half* VTs = Ks + 64 * ATT_KP;       // [128][72]

    int h  = blockIdx.y;
    int it = gridDim.x - 1 - blockIdx.x;  // big tiles first
    int i0 = it * 128;
    int hk = h >> 1;                      // NREP = 2
    int tid = threadIdx.x, wid = tid >> 5, lane = tid & 31;
    int lr = lane >> 2, lc = lane & 3;
    int wrow = wid * 16;

    // load Q tile (pre-scaled fp16)
    for (int idx = tid; idx < 2048; idx += 256) {
        int r = idx >> 4, ch = idx & 15;
        *(uint4*)&Qs[r * ATT_QP + ch * 8] =
            *(const uint4*)(Qh + ((size_t)(i0 + r) * HH + h) * DD + ch * 8);
    }

    float m_r0 = -1e30f, m_r1 = -1e30f, l_r0 = 0.f, l_r1 = 0.f;
    float oacc[16][4] = {};

    int nk = 2 * it + 2;
    for (int kt = 0; kt < nk; kt++) {
        int j0 = kt * 64;
        __syncthreads();
        for (int idx = tid; idx < 1024; idx += 256) {
            int r = idx >> 4, ch = idx & 15;
            *(uint4*)&Ks[r * ATT_KP + ch * 8] =
                *(const uint4*)(Kh + ((size_t)(j0 + r) * HKV + hk) * DD + ch * 8);
        }
        for (int idx = tid; idx < 1024; idx += 256) {
            int d = idx >> 3, ch = idx & 7;
            *(uint4*)&VTs[d * ATT_VP + ch * 8] =
                *(const uint4*)(VTh + ((size_t)hk * DD + d) * TT + j0 + ch * 8);
        }
        __syncthreads();

        // S = Q K^T : warp computes 16 x 64, k = 128
        float sacc[8][4] = {};
        #pragma unroll
        for (int ks = 0; ks < 8; ks++) {
            int k0 = ks * 16;
            uint32_t a[4];
            const __half* ap = Qs + (wrow + lr) * ATT_QP + k0 + 2 * lc;
            a[0] = *(const uint32_t*)(ap);
            a[1] = *(const uint32_t*)(ap + 8 * ATT_QP);
            a[2] = *(const uint32_t*)(ap + 8);
            a[3] = *(const uint32_t*)(ap + 8 * ATT_QP + 8);
            #pragma unroll
            for (int nf = 0; nf < 8; nf++) {
                uint32_t b[2];
                const __half* bp = Ks + (nf * 8 + lr) * ATT_KP + k0 + 2 * lc;
                b[0] = *(const uint32_t*)(bp);
                b[1] = *(const uint32_t*)(bp + 8);
                MMA_F16(sacc[nf], a, b);
            }
        }
        // causal mask (only the last two tiles touch the diagonal)
        if (kt >= nk - 2) {
            int r0g = i0 + wrow + lr;
            #pragma unroll
            for (int nf = 0; nf < 8; nf++) {
                int col = j0 + nf * 8 + 2 * lc;
                if (col     > r0g)     sacc[nf][0] = -1e30f;
                if (col + 1 > r0g)     sacc[nf][1] = -1e30f;
                if (col     > r0g + 8) sacc[nf][2] = -1e30f;
                if (col + 1 > r0g + 8) sacc[nf][3] = -1e30f;
            }
        }
        // online softmax (rows lr and lr+8; stats shared across 4-lane group)
        float mx0 = m_r0, mx1 = m_r1;
        #pragma unroll
        for (int nf = 0; nf < 8; nf++) {
            mx0 = fmaxf(mx0, fmaxf(sacc[nf][0], sacc[nf][1]));
            mx1 = fmaxf(mx1, fmaxf(sacc[nf][2], sacc[nf][3]));
        }
        mx0 = fmaxf(mx0, __shfl_xor_sync(0xffffffffu, mx0, 1));
        mx0 = fmaxf(mx0, __shfl_xor_sync(0xffffffffu, mx0, 2));
        mx1 = fmaxf(mx1, __shfl_xor_sync(0xffffffffu, mx1, 1));
        mx1 = fmaxf(mx1, __shfl_xor_sync(0xffffffffu, mx1, 2));
        float al0 = __expf(m_r0 - mx0), al1 = __expf(m_r1 - mx1);
        m_r0 = mx0; m_r1 = mx1;
        float s0 = 0.f, s1 = 0.f;
        uint32_t pf[8][2];
        #pragma unroll
        for (int nf = 0; nf < 8; nf++) {
            float p0 = __expf(sacc[nf][0] - mx0);
            float p1 = __expf(sacc[nf][1] - mx0);
            float p2 = __expf(sacc[nf][2] - mx1);
            float p3 = __expf(sacc[nf][3] - mx1);
            s0 += p0 + p1; s1 += p2 + p3;
            __half2 h01 = __floats2half2_rn(p0, p1);
            __half2 h23 = __floats2half2_rn(p2, p3);
            pf[nf][0] = *(uint32_t*)&h01;
            pf[nf][1] = *(uint32_t*)&h23;
        }
        s0 += __shfl_xor_sync(0xffffffffu, s0, 1);
        s0 += __shfl_xor_sync(0xffffffffu, s0, 2);
        s1 += __shfl_xor_sync(0xffffffffu, s1, 1);
        s1 += __shfl_xor_sync(0xffffffffu, s1, 2);
        l_r0 = l_r0 * al0 + s0;
        l_r1 = l_r1 * al1 + s1;
        #pragma unroll
        for (int nf = 0; nf < 16; nf++) {
            oacc[nf][0] *= al0; oacc[nf][1] *= al0;
            oacc[nf][2] *= al1; oacc[nf][3] *= al1;
        }
        // O += P V   (P in registers as A-fragments)
        #pragma unroll
        for (int ks = 0; ks < 4; ks++) {
            uint32_t a[4] = { pf[2 * ks][0], pf[2 * ks][1],
                              pf[2 * ks + 1][0], pf[2 * ks + 1][1] };
            #pragma unroll
            for (int nf = 0; nf < 16; nf++) {
                uint32_t b[2];
                const __half* bp = VTs + (nf * 8 + lr) * ATT_VP + 16 * ks + 2 * lc;
                b[0] = *(const uint32_t*)(bp);
                b[1] = *(const uint32_t*)(bp + 8);
                MMA_F16(oacc[nf], a, b);
            }
        }
    }
    // epilogue: normalize, fp16 store
    float inv0 = 1.f / l_r0, inv1 = 1.f / l_r1;
    #pragma unroll
    for (int nf = 0; nf < 16; nf++) {
        int d = nf * 8 + 2 * lc;
        __half2 o0 = __floats2half2_rn(oacc[nf][0] * inv0, oacc[nf][1] * inv0);
        __half2 o1 = __floats2half2_rn(oacc[nf][2] * inv1, oacc[nf][3] * inv1);
        *(uint32_t*)(O + ((size_t)(i0 + wrow + lr) * HH + h) * DD + d) = *(uint32_t*)&o0;
        *(uint32_t*)(O + ((size_t)(i0 + wrow + lr + 8) * HH + h) * DD + d) = *(uint32_t*)&o1;
    }
}

// ---------------- silu(gate) * up, fp16 output ----------------
__global__ void silu_mul_h(const float* __restrict__ gu, __half* __restrict__ act) {
    int idx4 = blockIdx.x * blockDim.x + threadIdx.x;
    int e0 = idx4 << 2;
    int t = e0 >> 13;
    int i = e0 & 8191;
    float4 g = *(const float4*)(gu + (size_t)t * (2 * II) + i);
    float4 u = *(const float4*)(gu + (size_t)t * (2 * II) + II + i);
    float a0 = g.x / (1.f + __expf(-g.x)) * u.x;
    float a1 = g.y / (1.f + __expf(-g.y)) * u.y;
    float a2 = g.z / (1.f + __expf(-g.z)) * u.z;
    float a3 = g.w / (1.f + __expf(-g.w)) * u.w;
    __half2 h0 = __floats2half2_rn(a0, a1);
    __half2 h1 = __floats2half2_rn(a2, a3);
    *(uint2*)(act + (size_t)t * II + i) = make_uint2(*(uint32_t*)&h0, *(uint32_t*)&h1);
}

// ---------------- launch ----------------
extern "C" void kernel_launch(void* const* d_in, const int* in_sizes, int n_in,
                              void* d_out, int out_size) {
    const float* hc    = (const float*)d_in[0];
    const float* cosT  = (const float*)d_in[1];
    const float* sinT  = (const float*)d_in[2];
    const float* wq    = (const float*)d_in[5];
    const float* wk    = (const float*)d_in[6];
    const float* wv    = (const float*)d_in[7];
    const float* wo    = (const float*)d_in[8];
    const float* wgu   = (const float*)d_in[9];
    const float* wd    = (const float*)d_in[10];
    const float* ilnw  = (const float*)d_in[11];
    const float* plnw  = (const float*)d_in[12];
    const float* qnw   = (const float*)d_in[13];
    const float* knw   = (const float*)d_in[14];
    float* out = (float*)d_out;

    float *px, *pq, *pk, *pv, *phid, *pgu;
    __half *phh, *patth, *ph2h, *pacth, *pqh, *pkh, *pvth;
    __half *pwqkv, *pwo, *pwgu, *pwd;
    cudaGetSymbolAddress((void**)&px,    g_x);
    cudaGetSymbolAddress((void**)&pq,    g_q);
    cudaGetSymbolAddress((void**)&pk,    g_k);
    cudaGetSymbolAddress((void**)&pv,    g_v);
    cudaGetSymbolAddress((void**)&phid,  g_hid);
    cudaGetSymbolAddress((void**)&pgu,   g_gu);
    cudaGetSymbolAddress((void**)&phh,   g_h_h);
    cudaGetSymbolAddress((void**)&patth, g_att_h);
    cudaGetSymbolAddress((void**)&ph2h,  g_h2_h);
    cudaGetSymbolAddress((void**)&pacth, g_act_h);
    cudaGetSymbolAddress((void**)&pqh,   g_q_h);
    cudaGetSymbolAddress((void**)&pkh,   g_k_h);
    cudaGetSymbolAddress((void**)&pvth,  g_vt_h);
    cudaGetSymbolAddress((void**)&pwqkv, g_wqkv_h);
    cudaGetSymbolAddress((void**)&pwo,   g_wo_h);
    cudaGetSymbolAddress((void**)&pwgu,  g_wgu_h);
    cudaGetSymbolAddress((void**)&pwd,   g_wd_h);

    cudaFuncSetAttribute(flash_attn_h, cudaFuncAttributeMaxDynamicSharedMemorySize, ATT_SMEM);
    cudaFuncSetAttribute(gemm_f16<true>,  cudaFuncAttributeMaxDynamicSharedMemorySize, SMEM_F16);
    cudaFuncSetAttribute(gemm_f16<false>, cudaFuncAttributeMaxDynamicSharedMemorySize, SMEM_F16);

    dim3 tb(32, 8);

    // 0. convert weights to fp16
    cvt_f16<<<(2048 * 2048 / 8) / 256, 256>>>((const float4*)wq,  (uint4*)pwqkv, 2048 * 2048 / 8);
    cvt_f16<<<(1024 * 2048 / 8) / 256, 256>>>((const float4*)wk,  (uint4*)(pwqkv + 2048 * 2048), 1024 * 2048 / 8);
    cvt_f16<<<(1024 * 2048 / 8) / 256, 256>>>((const float4*)wv,  (uint4*)(pwqkv + 3072 * 2048), 1024 * 2048 / 8);
    cvt_f16<<<(2048 * 2048 / 8) / 256, 256>>>((const float4*)wo,  (uint4*)pwo,  2048 * 2048 / 8);
    cvt_f16<<<(16384 * 2048 / 8) / 256, 256>>>((const float4*)wgu, (uint4*)pwgu, 16384 * 2048 / 8);
    cvt_f16<<<(2048 * 8192 / 8) / 256, 256>>>((const float4*)wd,  (uint4*)pwd,  2048 * 8192 / 8);

    // 1. x = hidden_conv^T
    transpose_k<<<dim3(TT / 32, HID / 32), tb>>>(hc, px, HID, TT);
    // 2. h = rms(x) * input_ln_w -> fp16
    rms_rows_h<<<TT, 256>>>(px, ilnw, phh, HID);
    // 3. fused QKV projection
    gemm_f16<true><<<dim3(32, 16), 256, SMEM_F16>>>(
        phh, pwqkv, nullptr, pq, pk, pv, 4096, HID);
    // 4. q/k head-RMS + rope -> fp16 (q pre-scaled by 1/sqrt(D)); V transpose
    qk_rms_rope_h<<<dim3(HH,  TT), 128>>>(pq, qnw, cosT, sinT, pqh, SCALEF);
    qk_rms_rope_h<<<dim3(HKV, TT), 128>>>(pk, knw, cosT, sinT, pkh, 1.0f);
    v_trans_h<<<dim3(TT / 32, DD / 32, HKV), tb>>>(pv, pvth);
    // 5. tensor-core flash attention -> fp16 att
    flash_attn_h<<<dim3(TT / 128, HH), 256, ATT_SMEM>>>(pqh, pkh, pvth, patth);
    // 6. hidden = x + att @ wo^T
    gemm_f16<false><<<dim3(16, 16), 256, SMEM_F16>>>(
        patth, pwo, px, phid, nullptr, nullptr, HID, HH * DD);
    // 7. h2 = rms(hidden) * post_ln_w -> fp16
    rms_rows_h<<<TT, 256>>>(phid, plnw, ph2h, HID);
    // 8. gate_up
    gemm_f16<false><<<dim3(128, 16), 256, SMEM_F16>>>(
        ph2h, pwgu, nullptr, pgu, nullptr, nullptr, 2 * II, HID);
    // 9. act = silu(gate) * up -> fp16
    silu_mul_h<<<(TT * II / 4) / 256, 256>>>(pgu, pacth);
    // 10. hidden += act @ w_down^T
    gemm_f16<false><<<dim3(16, 16), 256, SMEM_F16>>>(
        pacth, pwd, phid, phid, nullptr, nullptr, HID, II);
    // 11. out = hidden^T
    transpose_k<<<dim3(HID / 32, TT / 32), tb>>>(phid, out, TT, HID);
}

// round 8
// speedup vs baseline: 3.9120x; 1.6516x over previous
#include <cuda_runtime.h>
#include <cuda_bf16.h>
#include <cuda_fp16.h>
#include <cstdint>
#include <math.h>

// ---------------- problem constants ----------------
#define HH   16        // H
#define HKV  8
#define DD   128       // D
#define TT   2048      // T
#define HID  2048
#define II   8192      // I
#define NREP 2
#define EPSF 1e-6f
#define SCALEF 0.08838834764831845f   // 1/sqrt(128)

// ---------------- scratch (device globals, no allocs) ----------------
__device__ float g_x  [TT * HID];
__device__ float g_q  [TT * HH  * DD];
__device__ float g_k  [TT * HKV * DD];
__device__ float g_v  [TT * HKV * DD];
__device__ float g_hid[TT * HID];
// fp16 activation buffers
__device__ __align__(16) __half g_h_h  [TT * HID];
__device__ __align__(16) __half g_att_h[TT * HH * DD];
__device__ __align__(16) __half g_h2_h [TT * HID];
__device__ __align__(16) __half g_act_h[TT * II];
__device__ __align__(16) __half g_q_h  [TT * HH * DD];
__device__ __align__(16) __half g_k_h  [TT * HKV * DD];
__device__ __align__(16) __half g_vt_h [HKV * DD * TT];   // [hk][d][t]
// fp16 weights (converted every replay)
__device__ __align__(16) __half g_wqkv_h[4096 * HID];
__device__ __align__(16) __half g_wgu_h [2 * II * HID];   // gate/up row-interleaved
__device__ __align__(16) __half g_wo_h  [HID * HH * DD];
__device__ __align__(16) __half g_wd_h  [HID * II];

// ---------------- fp32 -> fp16 conversion (8 floats / thread) ----------------
__global__ void cvt_f16(const float4* __restrict__ src, uint4* __restrict__ dst, int n8) {
    int i = blockIdx.x * blockDim.x + threadIdx.x;
    if (i < n8) {
        float4 a = src[2 * i], b = src[2 * i + 1];
        __half2 h0 = __floats2half2_rn(a.x, a.y);
        __half2 h1 = __floats2half2_rn(a.z, a.w);
        __half2 h2 = __floats2half2_rn(b.x, b.y);
        __half2 h3 = __floats2half2_rn(b.z, b.w);
        dst[i] = make_uint4(*(uint32_t*)&h0, *(uint32_t*)&h1,
                            *(uint32_t*)&h2, *(uint32_t*)&h3);
    }
}

// wgu conversion with gate/up row interleave: dst row 2j = src row j (gate),
// dst row 2j+1 = src row I+j (up). Rows are HID=2048 floats = 256 chunks of 8.
__global__ void cvt_f16_gu(const float4* __restrict__ src, uint4* __restrict__ dst) {
    int i = blockIdx.x * blockDim.x + threadIdx.x;   // over 16384*256
    int row = i >> 8, chunk = i & 255;
    int drow = (row < II) ? (row << 1) : (((row - II) << 1) | 1);
    float4 a = src[2 * i], b = src[2 * i + 1];
    __half2 h0 = __floats2half2_rn(a.x, a.y);
    __half2 h1 = __floats2half2_rn(a.z, a.w);
    __half2 h2 = __floats2half2_rn(b.x, b.y);
    __half2 h3 = __floats2half2_rn(b.z, b.w);
    dst[drow * 256 + chunk] = make_uint4(*(uint32_t*)&h0, *(uint32_t*)&h1,
                                         *(uint32_t*)&h2, *(uint32_t*)&h3);
}

// ---------------- transpose: src[R][C] -> dst[C][R] ----------------
__global__ void transpose_k(const float* __restrict__ src, float* __restrict__ dst,
                            int R, int C) {
    __shared__ float tile[32][33];
    int r0 = blockIdx.y * 32, c0 = blockIdx.x * 32;
    int tx = threadIdx.x, ty = threadIdx.y;
    #pragma unroll
    for (int i = ty; i < 32; i += 8)
        tile[i][tx] = src[(size_t)(r0 + i) * C + c0 + tx];
    __syncthreads();
    #pragma unroll
    for (int i = ty; i < 32; i += 8)
        dst[(size_t)(c0 + i) * R + r0 + tx] = tile[tx][i];
}

// ---------------- V transpose+convert: [T][HKV][D] f32 -> [hk][d][t] f16 -----
__global__ void v_trans_h(const float* __restrict__ V, __half* __restrict__ VT) {
    __shared__ __half tile[32][33];
    int t0 = blockIdx.x * 32, d0 = blockIdx.y * 32, hk = blockIdx.z;
    int tx = threadIdx.x, ty = threadIdx.y;
    #pragma unroll
    for (int i = ty; i < 32; i += 8)
        tile[i][tx] = __float2half(V[((size_t)(t0 + i) * HKV + hk) * DD + d0 + tx]);
    __syncthreads();
    #pragma unroll
    for (int i = ty; i < 32; i += 8)
        VT[((size_t)hk * DD + d0 + i) * TT + t0 + tx] = tile[tx][i];
}

// ---------------- row RMS norm, fp16 output ----------------
__global__ void rms_rows_h(const float* __restrict__ X, const float* __restrict__ w,
                           __half* __restrict__ Y, int C) {
    int t = blockIdx.x;
    const float4* x4 = (const float4*)(X + (size_t)t * C);
    const float4* w4 = (const float4*)w;
    __half2*      y2 = (__half2*)(Y + (size_t)t * C);
    int n4 = C >> 2;
    float4 v[4];
    float ss = 0.f;
    int cnt = 0;
    for (int i = threadIdx.x; i < n4; i += 256) {
        float4 a = x4[i];
        v[cnt++] = a;
        ss += a.x * a.x + a.y * a.y + a.z * a.z + a.w * a.w;
    }
    #pragma unroll
    for (int o = 16; o; o >>= 1) ss += __shfl_xor_sync(0xffffffffu, ss, o);
    __shared__ float warpsum[8];
    if ((threadIdx.x & 31) == 0) warpsum[threadIdx.x >> 5] = ss;
    __syncthreads();
    ss = 0.f;
    #pragma unroll
    for (int i = 0; i < 8; i++) ss += warpsum[i];
    float r = rsqrtf(ss / (float)C + EPSF);
    cnt = 0;
    for (int i = threadIdx.x; i < n4; i += 256) {
        float4 a = v[cnt++];
        float4 ww = w4[i];
        y2[2 * i]     = __floats2half2_rn(a.x * r * ww.x, a.y * r * ww.y);
        y2[2 * i + 1] = __floats2half2_rn(a.z * r * ww.z, a.w * r * ww.w);
    }
}

// ---------------- per-head RMS + RoPE -> fp16 (optionally pre-scaled) --------
__global__ void qk_rms_rope_h(const float* __restrict__ buf, const float* __restrict__ w,
                              const float* __restrict__ cosT, const float* __restrict__ sinT,
                              __half* __restrict__ outp, float scale) {
    int h = blockIdx.x, t = blockIdx.y, nh = gridDim.x;
    const float* row = buf + ((size_t)t * nh + h) * DD;
    int d = threadIdx.x;
    float v = row[d];
    float ss = v * v;
    #pragma unroll
    for (int o = 16; o; o >>= 1) ss += __shfl_xor_sync(0xffffffffu, ss, o);
    __shared__ float wsum[4];
    if ((d & 31) == 0) wsum[d >> 5] = ss;
    __syncthreads();
    ss = wsum[0] + wsum[1] + wsum[2] + wsum[3];
    float r = rsqrtf(ss / 128.f + EPSF);
    float qn = v * r * w[d];
    __shared__ float sh[128];
    sh[d] = qn;
    __syncthreads();
    float rot = (d < 64) ? -sh[d + 64] : sh[d - 64];
    float val = (qn * cosT[(size_t)t * DD + d] + rot * sinT[(size_t)t * DD + d]) * scale;
    outp[((size_t)t * nh + h) * DD + d] = __float2half(val);
}

#define MMA_F16(d, a, b)                                                      \
    asm volatile("mma.sync.aligned.m16n8k16.row.col.f32.f16.f16.f32 "         \
                 "{%0,%1,%2,%3}, {%4,%5,%6,%7}, {%8,%9}, {%0,%1,%2,%3};"      \
                 : "+f"(d[0]), "+f"(d[1]), "+f"(d[2]), "+f"(d[3])             \
                 : "r"(a[0]), "r"(a[1]), "r"(a[2]), "r"(a[3]),                \
                   "r"(b[0]), "r"(b[1]))

#define LDSM_X4(r0, r1, r2, r3, addr)                                         \
    asm volatile("ldmatrix.sync.aligned.m8n8.x4.shared.b16 {%0,%1,%2,%3}, [%4];" \
                 : "=r"(r0), "=r"(r1), "=r"(r2), "=r"(r3) : "r"(addr))

// ---------------- fp16 tensor-core GEMM, cp.async 3-stage, ldmatrix ----------
// C[M,N] = A[M,K] * B[N,K]^T.  MODE 0: +Res optional. MODE 1: QKV routing.
// MODE 2: gate/up interleaved -> fused silu, fp16 output Ch [M][N/2].
#define HPITCH 40    // halfs per smem row (80 B): ldmatrix phases conflict-free
#define SMEM_F16 (3 * (128 + 128) * HPITCH * 2)   // 61440 B

template<int MODE>
__global__ __launch_bounds__(256, 2) void gemm_f16(
    const __half* __restrict__ A, const __half* __restrict__ B,
    const float* __restrict__ Res, float* __restrict__ C,
    float* __restrict__ Ck, float* __restrict__ Cv,
    __half* __restrict__ Ch,
    int N, int K) {
    constexpr int BM = 128, BN = 128;
    extern __shared__ __half shm[];
    __half* SA = shm;                     // [3][BM][HPITCH]
    __half* SB = shm + 3 * BM * HPITCH;   // [3][BN][HPITCH]

    const int bm = blockIdx.y * BM;
    const int bn = blockIdx.x * BN;
    const int tid = threadIdx.x;
    const int wid = tid >> 5, lane = tid & 31;
    const int wm = wid & 1, wn = wid >> 1;
    const int lr = lane >> 2, lc = lane & 3;
    const int nkt = K >> 5;

    // ldmatrix lane-address components
    const int amat = lane >> 3;                       // 0..3
    const int arow = ((amat & 1) << 3) + (lane & 7);  // +8 for odd matrices
    const int acol = (amat >> 1) << 3;                // +8 for matrices 2,3
    const int brow = ((amat >> 1) << 3) + (lane & 7); // B: matrices 2,3 are +8 rows
    const int bcol = (amat & 1) << 3;                 // B: odd matrices are +8 cols
    const uint32_t sa0 = (uint32_t)__cvta_generic_to_shared(SA);
    const uint32_t sb0 = (uint32_t)__cvta_generic_to_shared(SB);
    const uint32_t a_off = sa0 + ((wm * 64 + arow) * HPITCH + acol) * 2;
    const uint32_t b_off = sb0 + ((wn * 32 + brow) * HPITCH + bcol) * 2;

    auto issue = [&](int kt, int s) {
        int k0 = kt << 5;
        #pragma unroll
        for (int i = 0; i < 2; i++) {
            int cid = tid + i * 256;
            int r = cid >> 2, ch = cid & 3;
            const __half* g = A + (size_t)(bm + r) * K + k0 + ch * 8;
            uint32_t dst = (uint32_t)__cvta_generic_to_shared(
                &SA[(s * BM + r) * HPITCH + ch * 8]);
            asm volatile("cp.async.cg.shared.global [%0], [%1], 16;\n"
                         :: "r"(dst), "l"(g));
        }
        #pragma unroll
        for (int i = 0; i < 2; i++) {
            int cid = tid + i * 256;
            int r = cid >> 2, ch = cid & 3;
            const __half* g = B + (size_t)(bn + r) * K + k0 + ch * 8;
            uint32_t dst = (uint32_t)__cvta_generic_to_shared(
                &SB[(s * BN + r) * HPITCH + ch * 8]);
            asm volatile("cp.async.cg.shared.global [%0], [%1], 16;\n"
                         :: "r"(dst), "l"(g));
        }
        asm volatile("cp.async.commit_group;\n");
    };

    float acc[4][4][4] = {};

    issue(0, 0);
    issue(1, 1);

    for (int kt = 0; kt < nkt; kt++) {
        int s = kt % 3;
        if (kt == nkt - 1) { asm volatile("cp.async.wait_group 0;\n"); }
        else               { asm volatile("cp.async.wait_group 1;\n"); }
        __syncthreads();
        if (kt + 2 < nkt) issue(kt + 2, (kt + 2) % 3);

        uint32_t abase = a_off + s * (BM * HPITCH * 2);
        uint32_t bbase = b_off + s * (BN * HPITCH * 2);
        #pragma unroll
        for (int ks = 0; ks < 32; ks += 16) {
            uint32_t af[4][4], bf[4][2];
            #pragma unroll
            for (int mf = 0; mf < 4; mf++)
                LDSM_X4(af[mf][0], af[mf][1], af[mf][2], af[mf][3],
                        abase + (mf * 16 * HPITCH + ks) * 2);
            #pragma unroll
            for (int t = 0; t < 2; t++)
                LDSM_X4(bf[2 * t][0], bf[2 * t][1], bf[2 * t + 1][0], bf[2 * t + 1][1],
                        bbase + (t * 16 * HPITCH + ks) * 2);
            #pragma unroll
            for (int mf = 0; mf < 4; mf++)
                #pragma unroll
                for (int nf = 0; nf < 4; nf++)
                    MMA_F16(acc[mf][nf], af[mf], bf[nf]);
        }
    }

    if (MODE == 2) {
        // fused silu(gate)*up -> fp16, output width N/2
        #pragma unroll
        for (int mf = 0; mf < 4; mf++) {
            #pragma unroll
            for (int nf = 0; nf < 4; nf++) {
                int rg = bm + wm * 64 + mf * 16 + lr;
                int j = ((bn + wn * 32 + nf * 8) >> 1) + lc;
                float g0 = acc[mf][nf][0], u0 = acc[mf][nf][1];
                float g1 = acc[mf][nf][2], u1 = acc[mf][nf][3];
                Ch[(size_t)rg * (N / 2) + j] =
                    __float2half(g0 / (1.f + __expf(-g0)) * u0);
                Ch[(size_t)(rg + 8) * (N / 2) + j] =
                    __float2half(g1 / (1.f + __expf(-g1)) * u1);
            }
        }
        return;
    }

    float* Cb;
    int Nloc, cl0;
    if (MODE == 1) {
        if (bn < 2048)      { Cb = C;  Nloc = 2048; cl0 = bn; }
        else if (bn < 3072) { Cb = Ck; Nloc = 1024; cl0 = bn - 2048; }
        else                { Cb = Cv; Nloc = 1024; cl0 = bn - 3072; }
    } else {
        Cb = C; Nloc = N; cl0 = bn;
    }
    #pragma unroll
    for (int mf = 0; mf < 4; mf++) {
        #pragma unroll
        for (int nf = 0; nf < 4; nf++) {
            int rg = bm + wm * 64 + mf * 16 + lr;
            int cg = cl0 + wn * 32 + nf * 8 + 2 * lc;
            float2 v0 = make_float2(acc[mf][nf][0], acc[mf][nf][1]);
            float2 v1 = make_float2(acc[mf][nf][2], acc[mf][nf][3]);
            if (MODE == 0 && Res) {
                float2 r0 = *(const float2*)(Res + (size_t)rg * Nloc + cg);
                float2 r1 = *(const float2*)(Res + (size_t)(rg + 8) * Nloc + cg);
                v0.x += r0.x; v0.y += r0.y;
                v1.x += r1.x; v1.y += r1.y;
            }
            *(float2*)(Cb + (size_t)rg * Nloc + cg) = v0;
            *(float2*)(Cb + (size_t)(rg + 8) * Nloc + cg) = v1;
        }
    }
}

// ---------------- tensor-core flash attention ----------------
#define ATT_QP 136
#define ATT_KP 136
#define ATT_VP 72
#define ATT_SMEM ((128 * ATT_QP + 64 * ATT_KP + 128 * ATT_VP) * 2)  // 70656 B

__global__ __launch_bounds__(256, 1) void flash_attn_h(
    const __half* __restrict__ Qh, const __half* __restrict__ Kh,
    const __half* __restrict__ VTh, __half* __restrict__ O) {
    extern __shared__ __half sma[];
    __half* Qs  = sma;                    // [128][136]
    __half* Ks  = Qs + 128 * ATT_QP;      // [64][136]
    __half* VTs = Ks + 64 * ATT_KP;       // [128][72]

    int h  = blockIdx.y;
    int it = gridDim.x - 1 - blockIdx.x;  // big tiles first
    int i0 = it * 128;
    int hk = h >> 1;                      // NREP = 2
    int tid = threadIdx.x, wid = tid >> 5, lane = tid & 31;
    int lr = lane >> 2, lc = lane & 3;
    int wrow = wid * 16;

    for (int idx = tid; idx < 2048; idx += 256) {
        int r = idx >> 4, ch = idx & 15;
        *(uint4*)&Qs[r * ATT_QP + ch * 8] =
            *(const uint4*)(Qh + ((size_t)(i0 + r) * HH + h) * DD + ch * 8);
    }

    float m_r0 = -1e30f, m_r1 = -1e30f, l_r0 = 0.f, l_r1 = 0.f;
    float oacc[16][4] = {};

    int nk = 2 * it + 2;
    for (int kt = 0; kt < nk; kt++) {
        int j0 = kt * 64;
        __syncthreads();
        for (int idx = tid; idx < 1024; idx += 256) {
            int r = idx >> 4, ch = idx & 15;
            *(uint4*)&Ks[r * ATT_KP + ch * 8] =
                *(const uint4*)(Kh + ((size_t)(j0 + r) * HKV + hk) * DD + ch * 8);
        }
        for (int idx = tid; idx < 1024; idx += 256) {
            int d = idx >> 3, ch = idx & 7;
            *(uint4*)&VTs[d * ATT_VP + ch * 8] =
                *(const uint4*)(VTh + ((size_t)hk * DD + d) * TT + j0 + ch * 8);
        }
        __syncthreads();

        float sacc[8][4] = {};
        #pragma unroll
        for (int ks = 0; ks < 8; ks++) {
            int k0 = ks * 16;
            uint32_t a[4];
            const __half* ap = Qs + (wrow + lr) * ATT_QP + k0 + 2 * lc;
            a[0] = *(const uint32_t*)(ap);
            a[1] = *(const uint32_t*)(ap + 8 * ATT_QP);
            a[2] = *(const uint32_t*)(ap + 8);
            a[3] = *(const uint32_t*)(ap + 8 * ATT_QP + 8);
            #pragma unroll
            for (int nf = 0; nf < 8; nf++) {
                uint32_t b[2];
                const __half* bp = Ks + (nf * 8 + lr) * ATT_KP + k0 + 2 * lc;
                b[0] = *(const uint32_t*)(bp);
                b[1] = *(const uint32_t*)(bp + 8);
                MMA_F16(sacc[nf], a, b);
            }
        }
        if (kt >= nk - 2) {
            int r0g = i0 + wrow + lr;
            #pragma unroll
            for (int nf = 0; nf < 8; nf++) {
                int col = j0 + nf * 8 + 2 * lc;
                if (col     > r0g)     sacc[nf][0] = -1e30f;
                if (col + 1 > r0g)     sacc[nf][1] = -1e30f;
                if (col     > r0g + 8) sacc[nf][2] = -1e30f;
                if (col + 1 > r0g + 8) sacc[nf][3] = -1e30f;
            }
        }
        float mx0 = m_r0, mx1 = m_r1;
        #pragma unroll
        for (int nf = 0; nf < 8; nf++) {
            mx0 = fmaxf(mx0, fmaxf(sacc[nf][0], sacc[nf][1]));
            mx1 = fmaxf(mx1, fmaxf(sacc[nf][2], sacc[nf][3]));
        }
        mx0 = fmaxf(mx0, __shfl_xor_sync(0xffffffffu, mx0, 1));
        mx0 = fmaxf(mx0, __shfl_xor_sync(0xffffffffu, mx0, 2));
        mx1 = fmaxf(mx1, __shfl_xor_sync(0xffffffffu, mx1, 1));
        mx1 = fmaxf(mx1, __shfl_xor_sync(0xffffffffu, mx1, 2));
        float al0 = __expf(m_r0 - mx0), al1 = __expf(m_r1 - mx1);
        m_r0 = mx0; m_r1 = mx1;
        float s0 = 0.f, s1 = 0.f;
        uint32_t pf[8][2];
        #pragma unroll
        for (int nf = 0; nf < 8; nf++) {
            float p0 = __expf(sacc[nf][0] - mx0);
            float p1 = __expf(sacc[nf][1] - mx0);
            float p2 = __expf(sacc[nf][2] - mx1);
            float p3 = __expf(sacc[nf][3] - mx1);
            s0 += p0 + p1; s1 += p2 + p3;
            __half2 h01 = __floats2half2_rn(p0, p1);
            __half2 h23 = __floats2half2_rn(p2, p3);
            pf[nf][0] = *(uint32_t*)&h01;
            pf[nf][1] = *(uint32_t*)&h23;
        }
        s0 += __shfl_xor_sync(0xffffffffu, s0, 1);
        s0 += __shfl_xor_sync(0xffffffffu, s0, 2);
        s1 += __shfl_xor_sync(0xffffffffu, s1, 1);
        s1 += __shfl_xor_sync(0xffffffffu, s1, 2);
        l_r0 = l_r0 * al0 + s0;
        l_r1 = l_r1 * al1 + s1;
        #pragma unroll
        for (int nf = 0; nf < 16; nf++) {
            oacc[nf][0] *= al0; oacc[nf][1] *= al0;
            oacc[nf][2] *= al1; oacc[nf][3] *= al1;
        }
        #pragma unroll
        for (int ks = 0; ks < 4; ks++) {
            uint32_t a[4] = { pf[2 * ks][0], pf[2 * ks][1],
                              pf[2 * ks + 1][0], pf[2 * ks + 1][1] };
            #pragma unroll
            for (int nf = 0; nf < 16; nf++) {
                uint32_t b[2];
                const __half* bp = VTs + (nf * 8 + lr) * ATT_VP + 16 * ks + 2 * lc;
                b[0] = *(const uint32_t*)(bp);
                b[1] = *(const uint32_t*)(bp + 8);
                MMA_F16(oacc[nf], a, b);
            }
        }
    }
    float inv0 = 1.f / l_r0, inv1 = 1.f / l_r1;
    #pragma unroll
    for (int nf = 0; nf < 16; nf++) {
        int d = nf * 8 + 2 * lc;
        __half2 o0 = __floats2half2_rn(oacc[nf][0] * inv0, oacc[nf][1] * inv0);
        __half2 o1 = __floats2half2_rn(oacc[nf][2] * inv1, oacc[nf][3] * inv1);
        *(uint32_t*)(O + ((size_t)(i0 + wrow + lr) * HH + h) * DD + d) = *(uint32_t*)&o0;
        *(uint32_t*)(O + ((size_t)(i0 + wrow + lr + 8) * HH + h) * DD + d) = *(uint32_t*)&o1;
    }
}

// ---------------- launch ----------------
extern "C" void kernel_launch(void* const* d_in, const int* in_sizes, int n_in,
                              void* d_out, int out_size) {
    const float* hc    = (const float*)d_in[0];
    const float* cosT  = (const float*)d_in[1];
    const float* sinT  = (const float*)d_in[2];
    const float* wq    = (const float*)d_in[5];
    const float* wk    = (const float*)d_in[6];
    const float* wv    = (const float*)d_in[7];
    const float* wo    = (const float*)d_in[8];
    const float* wgu   = (const float*)d_in[9];
    const float* wd    = (const float*)d_in[10];
    const float* ilnw  = (const float*)d_in[11];
    const float* plnw  = (const float*)d_in[12];
    const float* qnw   = (const float*)d_in[13];
    const float* knw   = (const float*)d_in[14];
    float* out = (float*)d_out;

    float *px, *pq, *pk, *pv, *phid;
    __half *phh, *patth, *ph2h, *pacth, *pqh, *pkh, *pvth;
    __half *pwqkv, *pwo, *pwgu, *pwd;
    cudaGetSymbolAddress((void**)&px,    g_x);
    cudaGetSymbolAddress((void**)&pq,    g_q);
    cudaGetSymbolAddress((void**)&pk,    g_k);
    cudaGetSymbolAddress((void**)&pv,    g_v);
    cudaGetSymbolAddress((void**)&phid,  g_hid);
    cudaGetSymbolAddress((void**)&phh,   g_h_h);
    cudaGetSymbolAddress((void**)&patth, g_att_h);
    cudaGetSymbolAddress((void**)&ph2h,  g_h2_h);
    cudaGetSymbolAddress((void**)&pacth, g_act_h);
    cudaGetSymbolAddress((void**)&pqh,   g_q_h);
    cudaGetSymbolAddress((void**)&pkh,   g_k_h);
    cudaGetSymbolAddress((void**)&pvth,  g_vt_h);
    cudaGetSymbolAddress((void**)&pwqkv, g_wqkv_h);
    cudaGetSymbolAddress((void**)&pwo,   g_wo_h);
    cudaGetSymbolAddress((void**)&pwgu,  g_wgu_h);
    cudaGetSymbolAddress((void**)&pwd,   g_wd_h);

    cudaFuncSetAttribute(flash_attn_h, cudaFuncAttributeMaxDynamicSharedMemorySize, ATT_SMEM);
    cudaFuncSetAttribute(gemm_f16<0>, cudaFuncAttributeMaxDynamicSharedMemorySize, SMEM_F16);
    cudaFuncSetAttribute(gemm_f16<1>, cudaFuncAttributeMaxDynamicSharedMemorySize, SMEM_F16);
    cudaFuncSetAttribute(gemm_f16<2>, cudaFuncAttributeMaxDynamicSharedMemorySize, SMEM_F16);

    dim3 tb(32, 8);

    // 0. convert weights to fp16 (wgu with gate/up interleave)
    cvt_f16<<<(2048 * 2048 / 8) / 256, 256>>>((const float4*)wq,  (uint4*)pwqkv, 2048 * 2048 / 8);
    cvt_f16<<<(1024 * 2048 / 8) / 256, 256>>>((const float4*)wk,  (uint4*)(pwqkv + 2048 * 2048), 1024 * 2048 / 8);
    cvt_f16<<<(1024 * 2048 / 8) / 256, 256>>>((const float4*)wv,  (uint4*)(pwqkv + 3072 * 2048), 1024 * 2048 / 8);
    cvt_f16<<<(2048 * 2048 / 8) / 256, 256>>>((const float4*)wo,  (uint4*)pwo,  2048 * 2048 / 8);
    cvt_f16_gu<<<(16384 * 256) / 256, 256>>>((const float4*)wgu, (uint4*)pwgu);
    cvt_f16<<<(2048 * 8192 / 8) / 256, 256>>>((const float4*)wd,  (uint4*)pwd,  2048 * 8192 / 8);

    // 1. x = hidden_conv^T
    transpose_k<<<dim3(TT / 32, HID / 32), tb>>>(hc, px, HID, TT);
    // 2. h = rms(x) * input_ln_w -> fp16
    rms_rows_h<<<TT, 256>>>(px, ilnw, phh, HID);
    // 3. fused QKV projection
    gemm_f16<1><<<dim3(32, 16), 256, SMEM_F16>>>(
        phh, pwqkv, nullptr, pq, pk, pv, nullptr, 4096, HID);
    // 4. q/k head-RMS + rope -> fp16 (q pre-scaled); V transpose
    qk_rms_rope_h<<<dim3(HH,  TT), 128>>>(pq, qnw, cosT, sinT, pqh, SCALEF);
    qk_rms_rope_h<<<dim3(HKV, TT), 128>>>(pk, knw, cosT, sinT, pkh, 1.0f);
    v_trans_h<<<dim3(TT / 32, DD / 32, HKV), tb>>>(pv, pvth);
    // 5. tensor-core flash attention -> fp16 att
    flash_attn_h<<<dim3(TT / 128, HH), 256, ATT_SMEM>>>(pqh, pkh, pvth, patth);
    // 6. hidden = x + att @ wo^T
    gemm_f16<0><<<dim3(16, 16), 256, SMEM_F16>>>(
        patth, pwo, px, phid, nullptr, nullptr, nullptr, HID, HH * DD);
    // 7. h2 = rms(hidden) * post_ln_w -> fp16
    rms_rows_h<<<TT, 256>>>(phid, plnw, ph2h, HID);
    // 8. gate_up with fused silu -> fp16 act directly
    gemm_f16<2><<<dim3(128, 16), 256, SMEM_F16>>>(
        ph2h, pwgu, nullptr, nullptr, nullptr, nullptr, pacth, 2 * II, HID);
    // 9. hidden += act @ w_down^T
    gemm_f16<0><<<dim3(16, 16), 256, SMEM_F16>>>(
        pacth, pwd, phid, phid, nullptr, nullptr, nullptr, HID, II);
    // 10. out = hidden^T
    transpose_k<<<dim3(HID / 32, TT / 32), tb>>>(phid, out, TT, HID);
}

// round 10
// speedup vs baseline: 4.2220x; 1.0793x over previous
#include <cuda_runtime.h>
#include <cuda_bf16.h>
#include <cuda_fp16.h>
#include <cstdint>
#include <math.h>

// ---------------- problem constants ----------------
#define HH   16        // H
#define HKV  8
#define DD   128       // D
#define TT   2048      // T
#define HID  2048
#define II   8192      // I
#define NREP 2
#define EPSF 1e-6f
#define SCALEF 0.08838834764831845f   // 1/sqrt(128)

// ---------------- scratch (device globals, no allocs) ----------------
__device__ float g_x  [TT * HID];
__device__ float g_hid[TT * HID];
// fp16 activation buffers
__device__ __align__(16) __half g_h_h  [TT * HID];
__device__ __align__(16) __half g_att_h[TT * HH * DD];
__device__ __align__(16) __half g_h2_h [TT * HID];
__device__ __align__(16) __half g_act_h[TT * II];
__device__ __align__(16) __half g_q_h  [TT * HH * DD];   // raw qkv -> rope in place
__device__ __align__(16) __half g_k_h  [TT * HKV * DD];
__device__ __align__(16) __half g_v_h  [TT * HKV * DD];
__device__ __align__(16) __half g_vt_h [HKV * DD * TT];  // [hk][d][t]
// fp16 weights (converted every replay)
__device__ __align__(16) __half g_wqkv_h[4096 * HID];
__device__ __align__(16) __half g_wgu_h [2 * II * HID];  // gate/up row-interleaved
__device__ __align__(16) __half g_wo_h  [HID * HH * DD];
__device__ __align__(16) __half g_wd_h  [HID * II];

// ---------------- fp32 -> fp16 conversion (8 floats / thread) ----------------
__global__ void cvt_f16(const float4* __restrict__ src, uint4* __restrict__ dst, int n8) {
    int i = blockIdx.x * blockDim.x + threadIdx.x;
    if (i < n8) {
        float4 a = src[2 * i], b = src[2 * i + 1];
        __half2 h0 = __floats2half2_rn(a.x, a.y);
        __half2 h1 = __floats2half2_rn(a.z, a.w);
        __half2 h2 = __floats2half2_rn(b.x, b.y);
        __half2 h3 = __floats2half2_rn(b.z, b.w);
        dst[i] = make_uint4(*(uint32_t*)&h0, *(uint32_t*)&h1,
                            *(uint32_t*)&h2, *(uint32_t*)&h3);
    }
}

// wgu conversion with gate/up row interleave: dst row 2j = gate_j, 2j+1 = up_j.
__global__ void cvt_f16_gu(const float4* __restrict__ src, uint4* __restrict__ dst) {
    int i = blockIdx.x * blockDim.x + threadIdx.x;   // over 16384*256
    int row = i >> 8, chunk = i & 255;
    int drow = (row < II) ? (row << 1) : (((row - II) << 1) | 1);
    float4 a = src[2 * i], b = src[2 * i + 1];
    __half2 h0 = __floats2half2_rn(a.x, a.y);
    __half2 h1 = __floats2half2_rn(a.z, a.w);
    __half2 h2 = __floats2half2_rn(b.x, b.y);
    __half2 h3 = __floats2half2_rn(b.z, b.w);
    dst[drow * 256 + chunk] = make_uint4(*(uint32_t*)&h0, *(uint32_t*)&h1,
                                         *(uint32_t*)&h2, *(uint32_t*)&h3);
}

// ---------------- transpose: src[R][C] -> dst[C][R] (fp32) ----------------
__global__ void transpose_k(const float* __restrict__ src, float* __restrict__ dst,
                            int R, int C) {
    __shared__ float tile[32][33];
    int r0 = blockIdx.y * 32, c0 = blockIdx.x * 32;
    int tx = threadIdx.x, ty = threadIdx.y;
    #pragma unroll
    for (int i = ty; i < 32; i += 8)
        tile[i][tx] = src[(size_t)(r0 + i) * C + c0 + tx];
    __syncthreads();
    #pragma unroll
    for (int i = ty; i < 32; i += 8)
        dst[(size_t)(c0 + i) * R + r0 + tx] = tile[tx][i];
}

// ---------------- V transpose: [T][HKV][D] f16 -> [hk][d][t] f16 -----
__global__ void v_trans_h2(const __half* __restrict__ V, __half* __restrict__ VT) {
    __shared__ __half tile[32][33];
    int t0 = blockIdx.x * 32, d0 = blockIdx.y * 32, hk = blockIdx.z;
    int tx = threadIdx.x, ty = threadIdx.y;
    #pragma unroll
    for (int i = ty; i < 32; i += 8)
        tile[i][tx] = V[((size_t)(t0 + i) * HKV + hk) * DD + d0 + tx];
    __syncthreads();
    #pragma unroll
    for (int i = ty; i < 32; i += 8)
        VT[((size_t)hk * DD + d0 + i) * TT + t0 + tx] = tile[tx][i];
}

// ---------------- row RMS norm, fp16 output ----------------
__global__ void rms_rows_h(const float* __restrict__ X, const float* __restrict__ w,
                           __half* __restrict__ Y, int C) {
    int t = blockIdx.x;
    const float4* x4 = (const float4*)(X + (size_t)t * C);
    const float4* w4 = (const float4*)w;
    __half2*      y2 = (__half2*)(Y + (size_t)t * C);
    int n4 = C >> 2;
    float4 v[4];
    float ss = 0.f;
    int cnt = 0;
    for (int i = threadIdx.x; i < n4; i += 256) {
        float4 a = x4[i];
        v[cnt++] = a;
        ss += a.x * a.x + a.y * a.y + a.z * a.z + a.w * a.w;
    }
    #pragma unroll
    for (int o = 16; o; o >>= 1) ss += __shfl_xor_sync(0xffffffffu, ss, o);
    __shared__ float warpsum[8];
    if ((threadIdx.x & 31) == 0) warpsum[threadIdx.x >> 5] = ss;
    __syncthreads();
    ss = 0.f;
    #pragma unroll
    for (int i = 0; i < 8; i++) ss += warpsum[i];
    float r = rsqrtf(ss / (float)C + EPSF);
    cnt = 0;
    for (int i = threadIdx.x; i < n4; i += 256) {
        float4 a = v[cnt++];
        float4 ww = w4[i];
        y2[2 * i]     = __floats2half2_rn(a.x * r * ww.x, a.y * r * ww.y);
        y2[2 * i + 1] = __floats2half2_rn(a.z * r * ww.z, a.w * r * ww.w);
    }
}

// ---------------- per-head RMS + RoPE, fp16 in-place ----------------
__global__ void qk_rms_rope_h2(__half* __restrict__ buf, const float* __restrict__ w,
                               const float* __restrict__ cosT, const float* __restrict__ sinT,
                               float scale) {
    int h = blockIdx.x, t = blockIdx.y, nh = gridDim.x;
    __half* row = buf + ((size_t)t * nh + h) * DD;
    int d = threadIdx.x;
    float v = __half2float(row[d]);
    float ss = v * v;
    #pragma unroll
    for (int o = 16; o; o >>= 1) ss += __shfl_xor_sync(0xffffffffu, ss, o);
    __shared__ float wsum[4];
    if ((d & 31) == 0) wsum[d >> 5] = ss;
    __syncthreads();
    ss = wsum[0] + wsum[1] + wsum[2] + wsum[3];
    float r = rsqrtf(ss / 128.f + EPSF);
    float qn = v * r * w[d];
    __shared__ float sh[128];
    sh[d] = qn;
    __syncthreads();
    float rot = (d < 64) ? -sh[d + 64] : sh[d - 64];
    float val = (qn * cosT[(size_t)t * DD + d] + rot * sinT[(size_t)t * DD + d]) * scale;
    row[d] = __float2half(val);
}

#define MMA_F16(d, a, b)                                                      \
    asm volatile("mma.sync.aligned.m16n8k16.row.col.f32.f16.f16.f32 "         \
                 "{%0,%1,%2,%3}, {%4,%5,%6,%7}, {%8,%9}, {%0,%1,%2,%3};"      \
                 : "+f"(d[0]), "+f"(d[1]), "+f"(d[2]), "+f"(d[3])             \
                 : "r"(a[0]), "r"(a[1]), "r"(a[2]), "r"(a[3]),                \
                   "r"(b[0]), "r"(b[1]))

#define LDSM_X4(r0, r1, r2, r3, addr)                                         \
    asm volatile("ldmatrix.sync.aligned.m8n8.x4.shared.b16 {%0,%1,%2,%3}, [%4];" \
                 : "=r"(r0), "=r"(r1), "=r"(r2), "=r"(r3) : "r"(addr))

// ---------------- fp16 tensor-core GEMM, cp.async 3-stage, BK=64, ldmatrix ---
// C[M,N] = A[M,K] * B[N,K]^T.
// MODE 0: +Res, fp32 out.  MODE 1: QKV routing, fp16 out.
// MODE 2: gate/up interleaved -> fused silu, fp16 out [M][N/2].
// MODE 3: +Res, fp32 out TRANSPOSED ([N][T] layout, i.e. final hidden^T).
#define HPITCH 72    // halfs per smem row (144 B): ldmatrix 8-row phase conflict-free
#define SMEM_F16 (3 * (128 + 128) * HPITCH * 2)   // 110592 B

template<int MODE>
__global__ __launch_bounds__(256, 2) void gemm_f16(
    const __half* __restrict__ A, const __half* __restrict__ B,
    const float* __restrict__ Res, float* __restrict__ C,
    __half* __restrict__ H0, __half* __restrict__ H1, __half* __restrict__ H2,
    int N, int K) {
    constexpr int BM = 128, BN = 128;
    extern __shared__ __half shm[];
    __half* SA = shm;                     // [3][BM][HPITCH]
    __half* SB = shm + 3 * BM * HPITCH;   // [3][BN][HPITCH]

    const int bm = blockIdx.y * BM;
    const int bn = blockIdx.x * BN;
    const int tid = threadIdx.x;
    const int wid = tid >> 5, lane = tid & 31;
    const int wm = wid & 1, wn = wid >> 1;
    const int lr = lane >> 2, lc = lane & 3;
    const int nkt = K >> 6;

    // ldmatrix lane-address components
    const int amat = lane >> 3;
    const int arow = ((amat & 1) << 3) + (lane & 7);
    const int acol = (amat >> 1) << 3;
    const int brow = ((amat >> 1) << 3) + (lane & 7);
    const int bcol = (amat & 1) << 3;
    const uint32_t sa0 = (uint32_t)__cvta_generic_to_shared(SA);
    const uint32_t sb0 = (uint32_t)__cvta_generic_to_shared(SB);
    const uint32_t a_off = sa0 + ((wm * 64 + arow) * HPITCH + acol) * 2;
    const uint32_t b_off = sb0 + ((wn * 32 + brow) * HPITCH + bcol) * 2;

    auto issue = [&](int kt, int s) {
        int k0 = kt << 6;
        #pragma unroll
        for (int i = 0; i < 4; i++) {
            int cid = tid + i * 256;
            int r = cid >> 3, ch = cid & 7;          // 8 x 16B chunks per 128B row
            const __half* g = A + (size_t)(bm + r) * K + k0 + ch * 8;
            uint32_t dst = (uint32_t)__cvta_generic_to_shared(
                &SA[(s * BM + r) * HPITCH + ch * 8]);
            asm volatile("cp.async.cg.shared.global [%0], [%1], 16;\n"
                         :: "r"(dst), "l"(g));
        }
        #pragma unroll
        for (int i = 0; i < 4; i++) {
            int cid = tid + i * 256;
            int r = cid >> 3, ch = cid & 7;
            const __half* g = B + (size_t)(bn + r) * K + k0 + ch * 8;
            uint32_t dst = (uint32_t)__cvta_generic_to_shared(
                &SB[(s * BN + r) * HPITCH + ch * 8]);
            asm volatile("cp.async.cg.shared.global [%0], [%1], 16;\n"
                         :: "r"(dst), "l"(g));
        }
        asm volatile("cp.async.commit_group;\n");
    };

    float acc[4][4][4] = {};

    issue(0, 0);
    issue(1, 1);

    for (int kt = 0; kt < nkt; kt++) {
        int s = kt % 3;
        if (kt == nkt - 1) { asm volatile("cp.async.wait_group 0;\n"); }
        else               { asm volatile("cp.async.wait_group 1;\n"); }
        __syncthreads();
        if (kt + 2 < nkt) issue(kt + 2, (kt + 2) % 3);

        uint32_t abase = a_off + s * (BM * HPITCH * 2);
        uint32_t bbase = b_off + s * (BN * HPITCH * 2);
        #pragma unroll
        for (int ks = 0; ks < 64; ks += 16) {
            uint32_t af[4][4], bf[4][2];
            #pragma unroll
            for (int mf = 0; mf < 4; mf++)
                LDSM_X4(af[mf][0], af[mf][1], af[mf][2], af[mf][3],
                        abase + (mf * 16 * HPITCH + ks) * 2);
            #pragma unroll
            for (int t = 0; t < 2; t++)
                LDSM_X4(bf[2 * t][0], bf[2 * t][1], bf[2 * t + 1][0], bf[2 * t + 1][1],
                        bbase + (t * 16 * HPITCH + ks) * 2);
            #pragma unroll
            for (int mf = 0; mf < 4; mf++)
                #pragma unroll
                for (int nf = 0; nf < 4; nf++)
                    MMA_F16(acc[mf][nf], af[mf], bf[nf]);
        }
    }

    if (MODE == 1) {
        // fp16 QKV routing
        __half* Cb;
        int Nloc, cl0;
        if (bn < 2048)      { Cb = H0; Nloc = 2048; cl0 = bn; }
        else if (bn < 3072) { Cb = H1; Nloc = 1024; cl0 = bn - 2048; }
        else                { Cb = H2; Nloc = 1024; cl0 = bn - 3072; }
        #pragma unroll
        for (int mf = 0; mf < 4; mf++) {
            #pragma unroll
            for (int nf = 0; nf < 4; nf++) {
                int rg = bm + wm * 64 + mf * 16 + lr;
                int cg = cl0 + wn * 32 + nf * 8 + 2 * lc;
                __half2 v0 = __floats2half2_rn(acc[mf][nf][0], acc[mf][nf][1]);
                __half2 v1 = __floats2half2_rn(acc[mf][nf][2], acc[mf][nf][3]);
                *(__half2*)(Cb + (size_t)rg * Nloc + cg) = v0;
                *(__half2*)(Cb + (size_t)(rg + 8) * Nloc + cg) = v1;
            }
        }
        return;
    }
    if (MODE == 2) {
        #pragma unroll
        for (int mf = 0; mf < 4; mf++) {
            #pragma unroll
            for (int nf = 0; nf < 4; nf++) {
                int rg = bm + wm * 64 + mf * 16 + lr;
                int j = ((bn + wn * 32 + nf * 8) >> 1) + lc;
                float g0 = acc[mf][nf][0], u0 = acc[mf][nf][1];
                float g1 = acc[mf][nf][2], u1 = acc[mf][nf][3];
                H0[(size_t)rg * (N / 2) + j] =
                    __float2half(g0 / (1.f + __expf(-g0)) * u0);
                H0[(size_t)(rg + 8) * (N / 2) + j] =
                    __float2half(g1 / (1.f + __expf(-g1)) * u1);
            }
        }
        return;
    }
    if (MODE == 3) {
        // residual add + transposed fp32 store: C is [N][TT]
        #pragma unroll
        for (int mf = 0; mf < 4; mf++) {
            #pragma unroll
            for (int nf = 0; nf < 4; nf++) {
                int rg = bm + wm * 64 + mf * 16 + lr;
                int cg = bn + wn * 32 + nf * 8 + 2 * lc;
                float2 r0 = *(const float2*)(Res + (size_t)rg * N + cg);
                float2 r1 = *(const float2*)(Res + (size_t)(rg + 8) * N + cg);
                C[(size_t)cg * TT + rg]           = acc[mf][nf][0] + r0.x;
                C[(size_t)(cg + 1) * TT + rg]     = acc[mf][nf][1] + r0.y;
                C[(size_t)cg * TT + rg + 8]       = acc[mf][nf][2] + r1.x;
                C[(size_t)(cg + 1) * TT + rg + 8] = acc[mf][nf][3] + r1.y;
            }
        }
        return;
    }
    // MODE 0
    #pragma unroll
    for (int mf = 0; mf < 4; mf++) {
        #pragma unroll
        for (int nf = 0; nf < 4; nf++) {
            int rg = bm + wm * 64 + mf * 16 + lr;
            int cg = bn + wn * 32 + nf * 8 + 2 * lc;
            float2 v0 = make_float2(acc[mf][nf][0], acc[mf][nf][1]);
            float2 v1 = make_float2(acc[mf][nf][2], acc[mf][nf][3]);
            if (Res) {
                float2 r0 = *(const float2*)(Res + (size_t)rg * N + cg);
                float2 r1 = *(const float2*)(Res + (size_t)(rg + 8) * N + cg);
                v0.x += r0.x; v0.y += r0.y;
                v1.x += r1.x; v1.y += r1.y;
            }
            *(float2*)(C + (size_t)rg * N + cg) = v0;
            *(float2*)(C + (size_t)(rg + 8) * N + cg) = v1;
        }
    }
}

// ---------------- tensor-core flash attention (mma.sync) ----------
#define ATT_QP 136
#define ATT_KP 136
#define ATT_VP 72
#define ATT_SMEM ((128 * ATT_QP + 64 * ATT_KP + 128 * ATT_VP) * 2)  // 70656 B

__global__ __launch_bounds__(256, 1) void flash_attn_h(
    const __half* __restrict__ Qh, const __half* __restrict__ Kh,
    const __half* __restrict__ VTh, __half* __restrict__ O) {
    extern __shared__ __half sma[];
    __half* Qs  = sma;                    // [128][136]
    __half* Ks  = Qs + 128 * ATT_QP;      // [64][136]
    __half* VTs = Ks + 64 * ATT_KP;       // [128][72]

    int h  = blockIdx.y;
    int it = gridDim.x - 1 - blockIdx.x;  // big tiles first
    int i0 = it * 128;
    int hk = h >> 1;                      // NREP = 2
    int tid = threadIdx.x, wid = tid >> 5, lane = tid & 31;
    int lr = lane >> 2, lc = lane & 3;
    int wrow = wid * 16;

    for (int idx = tid; idx < 2048; idx += 256) {
        int r = idx >> 4, ch = idx & 15;
        *(uint4*)&Qs[r * ATT_QP + ch * 8] =
            *(const uint4*)(Qh + ((size_t)(i0 + r) * HH + h) * DD + ch * 8);
    }

    float m_r0 = -1e30f, m_r1 = -1e30f, l_r0 = 0.f, l_r1 = 0.f;
    float oacc[16][4] = {};

    int nk = 2 * it + 2;
    for (int kt = 0; kt < nk; kt++) {
        int j0 = kt * 64;
        __syncthreads();
        for (int idx = tid; idx < 1024; idx += 256) {
            int r = idx >> 4, ch = idx & 15;
            *(uint4*)&Ks[r * ATT_KP + ch * 8] =
                *(const uint4*)(Kh + ((size_t)(j0 + r) * HKV + hk) * DD + ch * 8);
        }
        for (int idx = tid; idx < 1024; idx += 256) {
            int d = idx >> 3, ch = idx & 7;
            *(uint4*)&VTs[d * ATT_VP + ch * 8] =
                *(const uint4*)(VTh + ((size_t)hk * DD + d) * TT + j0 + ch * 8);
        }
        __syncthreads();

        float sacc[8][4] = {};
        #pragma unroll
        for (int ks = 0; ks < 8; ks++) {
            int k0 = ks * 16;
            uint32_t a[4];
            const __half* ap = Qs + (wrow + lr) * ATT_QP + k0 + 2 * lc;
            a[0] = *(const uint32_t*)(ap);
            a[1] = *(const uint32_t*)(ap + 8 * ATT_QP);
            a[2] = *(const uint32_t*)(ap + 8);
            a[3] = *(const uint32_t*)(ap + 8 * ATT_QP + 8);
            #pragma unroll
            for (int nf = 0; nf < 8; nf++) {
                uint32_t b[2];
                const __half* bp = Ks + (nf * 8 + lr) * ATT_KP + k0 + 2 * lc;
                b[0] = *(const uint32_t*)(bp);
                b[1] = *(const uint32_t*)(bp + 8);
                MMA_F16(sacc[nf], a, b);
            }
        }
        if (kt >= nk - 2) {
            int r0g = i0 + wrow + lr;
            #pragma unroll
            for (int nf = 0; nf < 8; nf++) {
                int col = j0 + nf * 8 + 2 * lc;
                if (col     > r0g)     sacc[nf][0] = -1e30f;
                if (col + 1 > r0g)     sacc[nf][1] = -1e30f;
                if (col     > r0g + 8) sacc[nf][2] = -1e30f;
                if (col + 1 > r0g + 8) sacc[nf][3] = -1e30f;
            }
        }
        float mx0 = m_r0, mx1 = m_r1;
        #pragma unroll
        for (int nf = 0; nf < 8; nf++) {
            mx0 = fmaxf(mx0, fmaxf(sacc[nf][0], sacc[nf][1]));
            mx1 = fmaxf(mx1, fmaxf(sacc[nf][2], sacc[nf][3]));
        }
        mx0 = fmaxf(mx0, __shfl_xor_sync(0xffffffffu, mx0, 1));
        mx0 = fmaxf(mx0, __shfl_xor_sync(0xffffffffu, mx0, 2));
        mx1 = fmaxf(mx1, __shfl_xor_sync(0xffffffffu, mx1, 1));
        mx1 = fmaxf(mx1, __shfl_xor_sync(0xffffffffu, mx1, 2));
        float al0 = __expf(m_r0 - mx0), al1 = __expf(m_r1 - mx1);
        m_r0 = mx0; m_r1 = mx1;
        float s0 = 0.f, s1 = 0.f;
        uint32_t pf[8][2];
        #pragma unroll
        for (int nf = 0; nf < 8; nf++) {
            float p0 = __expf(sacc[nf][0] - mx0);
            float p1 = __expf(sacc[nf][1] - mx0);
            float p2 = __expf(sacc[nf][2] - mx1);
            float p3 = __expf(sacc[nf][3] - mx1);
            s0 += p0 + p1; s1 += p2 + p3;
            __half2 h01 = __floats2half2_rn(p0, p1);
            __half2 h23 = __floats2half2_rn(p2, p3);
            pf[nf][0] = *(uint32_t*)&h01;
            pf[nf][1] = *(uint32_t*)&h23;
        }
        s0 += __shfl_xor_sync(0xffffffffu, s0, 1);
        s0 += __shfl_xor_sync(0xffffffffu, s0, 2);
        s1 += __shfl_xor_sync(0xffffffffu, s1, 1);
        s1 += __shfl_xor_sync(0xffffffffu, s1, 2);
        l_r0 = l_r0 * al0 + s0;
        l_r1 = l_r1 * al1 + s1;
        #pragma unroll
        for (int nf = 0; nf < 16; nf++) {
            oacc[nf][0] *= al0; oacc[nf][1] *= al0;
            oacc[nf][2] *= al1; oacc[nf][3] *= al1;
        }
        #pragma unroll
        for (int ks = 0; ks < 4; ks++) {
            uint32_t a[4] = { pf[2 * ks][0], pf[2 * ks][1],
                              pf[2 * ks + 1][0], pf[2 * ks + 1][1] };
            #pragma unroll
            for (int nf = 0; nf < 16; nf++) {
                uint32_t b[2];
                const __half* bp = VTs + (nf * 8 + lr) * ATT_VP + 16 * ks + 2 * lc;
                b[0] = *(const uint32_t*)(bp);
                b[1] = *(const uint32_t*)(bp + 8);
                MMA_F16(oacc[nf], a, b);
            }
        }
    }
    float inv0 = 1.f / l_r0, inv1 = 1.f / l_r1;
    #pragma unroll
    for (int nf = 0; nf < 16; nf++) {
        int d = nf * 8 + 2 * lc;
        __half2 o0 = __floats2half2_rn(oacc[nf][0] * inv0, oacc[nf][1] * inv0);
        __half2 o1 = __floats2half2_rn(oacc[nf][2] * inv1, oacc[nf][3] * inv1);
        *(uint32_t*)(O + ((size_t)(i0 + wrow + lr) * HH + h) * DD + d) = *(uint32_t*)&o0;
        *(uint32_t*)(O + ((size_t)(i0 + wrow + lr + 8) * HH + h) * DD + d) = *(uint32_t*)&o1;
    }
}

// ---------------- launch ----------------
extern "C" void kernel_launch(void* const* d_in, const int* in_sizes, int n_in,
                              void* d_out, int out_size) {
    const float* hc    = (const float*)d_in[0];
    const float* cosT  = (const float*)d_in[1];
    const float* sinT  = (const float*)d_in[2];
    const float* wq    = (const float*)d_in[5];
    const float* wk    = (const float*)d_in[6];
    const float* wv    = (const float*)d_in[7];
    const float* wo    = (const float*)d_in[8];
    const float* wgu   = (const float*)d_in[9];
    const float* wd    = (const float*)d_in[10];
    const float* ilnw  = (const float*)d_in[11];
    const float* plnw  = (const float*)d_in[12];
    const float* qnw   = (const float*)d_in[13];
    const float* knw   = (const float*)d_in[14];
    float* out = (float*)d_out;

    float *px, *phid;
    __half *phh, *patth, *ph2h, *pacth, *pqh, *pkh, *pvh, *pvth;
    __half *pwqkv, *pwo, *pwgu, *pwd;
    cudaGetSymbolAddress((void**)&px,    g_x);
    cudaGetSymbolAddress((void**)&phid,  g_hid);
    cudaGetSymbolAddress((void**)&phh,   g_h_h);
    cudaGetSymbolAddress((void**)&patth, g_att_h);
    cudaGetSymbolAddress((void**)&ph2h,  g_h2_h);
    cudaGetSymbolAddress((void**)&pacth, g_act_h);
    cudaGetSymbolAddress((void**)&pqh,   g_q_h);
    cudaGetSymbolAddress((void**)&pkh,   g_k_h);
    cudaGetSymbolAddress((void**)&pvh,   g_v_h);
    cudaGetSymbolAddress((void**)&pvth,  g_vt_h);
    cudaGetSymbolAddress((void**)&pwqkv, g_wqkv_h);
    cudaGetSymbolAddress((void**)&pwo,   g_wo_h);
    cudaGetSymbolAddress((void**)&pwgu,  g_wgu_h);
    cudaGetSymbolAddress((void**)&pwd,   g_wd_h);

    cudaFuncSetAttribute(flash_attn_h, cudaFuncAttributeMaxDynamicSharedMemorySize, ATT_SMEM);
    cudaFuncSetAttribute(gemm_f16<0>, cudaFuncAttributeMaxDynamicSharedMemorySize, SMEM_F16);
    cudaFuncSetAttribute(gemm_f16<1>, cudaFuncAttributeMaxDynamicSharedMemorySize, SMEM_F16);
    cudaFuncSetAttribute(gemm_f16<2>, cudaFuncAttributeMaxDynamicSharedMemorySize, SMEM_F16);
    cudaFuncSetAttribute(gemm_f16<3>, cudaFuncAttributeMaxDynamicSharedMemorySize, SMEM_F16);

    dim3 tb(32, 8);

    // 0. convert weights to fp16 (wgu with gate/up interleave)
    cvt_f16<<<(2048 * 2048 / 8) / 256, 256>>>((const float4*)wq,  (uint4*)pwqkv, 2048 * 2048 / 8);
    cvt_f16<<<(1024 * 2048 / 8) / 256, 256>>>((const float4*)wk,  (uint4*)(pwqkv + 2048 * 2048), 1024 * 2048 / 8);
    cvt_f16<<<(1024 * 2048 / 8) / 256, 256>>>((const float4*)wv,  (uint4*)(pwqkv + 3072 * 2048), 1024 * 2048 / 8);
    cvt_f16<<<(2048 * 2048 / 8) / 256, 256>>>((const float4*)wo,  (uint4*)pwo,  2048 * 2048 / 8);
    cvt_f16_gu<<<(16384 * 256) / 256, 256>>>((const float4*)wgu, (uint4*)pwgu);
    cvt_f16<<<(2048 * 8192 / 8) / 256, 256>>>((const float4*)wd,  (uint4*)pwd,  2048 * 8192 / 8);

    // 1. x = hidden_conv^T
    transpose_k<<<dim3(TT / 32, HID / 32), tb>>>(hc, px, HID, TT);
    // 2. h = rms(x) * input_ln_w -> fp16
    rms_rows_h<<<TT, 256>>>(px, ilnw, phh, HID);
    // 3. fused QKV projection -> fp16 q/k/v directly
    gemm_f16<1><<<dim3(32, 16), 256, SMEM_F16>>>(
        phh, pwqkv, nullptr, nullptr, pqh, pkh, pvh, 4096, HID);
    // 4. q/k head-RMS + rope in place (q pre-scaled); V transpose
    qk_rms_rope_h2<<<dim3(HH,  TT), 128>>>(pqh, qnw, cosT, sinT, SCALEF);
    qk_rms_rope_h2<<<dim3(HKV, TT), 128>>>(pkh, knw, cosT, sinT, 1.0f);
    v_trans_h2<<<dim3(TT / 32, DD / 32, HKV), tb>>>(pvh, pvth);
    // 5. tensor-core flash attention -> fp16 att
    flash_attn_h<<<dim3(TT / 128, HH), 256, ATT_SMEM>>>(pqh, pkh, pvth, patth);
    // 6. hidden = x + att @ wo^T
    gemm_f16<0><<<dim3(16, 16), 256, SMEM_F16>>>(
        patth, pwo, px, phid, nullptr, nullptr, nullptr, HID, HH * DD);
    // 7. h2 = rms(hidden) * post_ln_w -> fp16
    rms_rows_h<<<TT, 256>>>(phid, plnw, ph2h, HID);
    // 8. gate_up with fused silu -> fp16 act
    gemm_f16<2><<<dim3(128, 16), 256, SMEM_F16>>>(
        ph2h, pwgu, nullptr, nullptr, pacth, nullptr, nullptr, 2 * II, HID);
    // 9. out = (hidden + act @ w_down^T)^T  (residual + transposed store fused)
    gemm_f16<3><<<dim3(16, 16), 256, SMEM_F16>>>(
        pacth, pwd, phid, out, nullptr, nullptr, nullptr, HID, II);
}

// round 12
// speedup vs baseline: 4.5899x; 1.0871x over previous
#include <cuda_runtime.h>
#include <cuda_bf16.h>
#include <cuda_fp16.h>
#include <cstdint>
#include <math.h>

// ---------------- problem constants ----------------
#define HH   16        // H
#define HKV  8
#define DD   128       // D
#define TT   2048      // T
#define HID  2048
#define II   8192      // I
#define NREP 2
#define EPSF 1e-6f
#define SCALEF 0.08838834764831845f   // 1/sqrt(128)

// ---------------- scratch (device globals, no allocs) ----------------
__device__ float g_x  [TT * HID];
__device__ float g_hid[TT * HID];
// fp16 activation buffers
__device__ __align__(16) __half g_h_h  [TT * HID];
__device__ __align__(16) __half g_att_h[TT * HH * DD];
__device__ __align__(16) __half g_h2_h [TT * HID];
__device__ __align__(16) __half g_act_h[TT * II];
__device__ __align__(16) __half g_q_h  [TT * HH * DD];   // raw qkv -> rope in place
__device__ __align__(16) __half g_k_h  [TT * HKV * DD];
__device__ __align__(16) __half g_v_h  [TT * HKV * DD];
__device__ __align__(16) __half g_vt_h [HKV * DD * TT];  // [hk][d][t]
// fp16 weights (converted every replay)
__device__ __align__(16) __half g_wqkv_h[4096 * HID];
__device__ __align__(16) __half g_wgu_h [2 * II * HID];  // gate/up row-interleaved
__device__ __align__(16) __half g_wo_h  [HID * HH * DD];
__device__ __align__(16) __half g_wd_h  [HID * II];

// ---------------- fp32 -> fp16 conversion (8 floats / thread) ----------------
__global__ void cvt_f16(const float4* __restrict__ src, uint4* __restrict__ dst, int n8) {
    int i = blockIdx.x * blockDim.x + threadIdx.x;
    if (i < n8) {
        float4 a = src[2 * i], b = src[2 * i + 1];
        __half2 h0 = __floats2half2_rn(a.x, a.y);
        __half2 h1 = __floats2half2_rn(a.z, a.w);
        __half2 h2 = __floats2half2_rn(b.x, b.y);
        __half2 h3 = __floats2half2_rn(b.z, b.w);
        dst[i] = make_uint4(*(uint32_t*)&h0, *(uint32_t*)&h1,
                            *(uint32_t*)&h2, *(uint32_t*)&h3);
    }
}

// wgu conversion with gate/up row interleave: dst row 2j = gate_j, 2j+1 = up_j.
__global__ void cvt_f16_gu(const float4* __restrict__ src, uint4* __restrict__ dst) {
    int i = blockIdx.x * blockDim.x + threadIdx.x;   // over 16384*256
    int row = i >> 8, chunk = i & 255;
    int drow = (row < II) ? (row << 1) : (((row - II) << 1) | 1);
    float4 a = src[2 * i], b = src[2 * i + 1];
    __half2 h0 = __floats2half2_rn(a.x, a.y);
    __half2 h1 = __floats2half2_rn(a.z, a.w);
    __half2 h2 = __floats2half2_rn(b.x, b.y);
    __half2 h3 = __floats2half2_rn(b.z, b.w);
    dst[drow * 256 + chunk] = make_uint4(*(uint32_t*)&h0, *(uint32_t*)&h1,
                                         *(uint32_t*)&h2, *(uint32_t*)&h3);
}

// ---------------- transpose: src[R][C] -> dst[C][R] (fp32) ----------------
__global__ void transpose_k(const float* __restrict__ src, float* __restrict__ dst,
                            int R, int C) {
    __shared__ float tile[32][33];
    int r0 = blockIdx.y * 32, c0 = blockIdx.x * 32;
    int tx = threadIdx.x, ty = threadIdx.y;
    #pragma unroll
    for (int i = ty; i < 32; i += 8)
        tile[i][tx] = src[(size_t)(r0 + i) * C + c0 + tx];
    __syncthreads();
    #pragma unroll
    for (int i = ty; i < 32; i += 8)
        dst[(size_t)(c0 + i) * R + r0 + tx] = tile[tx][i];
}

// ---------------- V transpose: [T][HKV][D] f16 -> [hk][d][t] f16 -----
__global__ void v_trans_h2(const __half* __restrict__ V, __half* __restrict__ VT) {
    __shared__ __half tile[32][33];
    int t0 = blockIdx.x * 32, d0 = blockIdx.y * 32, hk = blockIdx.z;
    int tx = threadIdx.x, ty = threadIdx.y;
    #pragma unroll
    for (int i = ty; i < 32; i += 8)
        tile[i][tx] = V[((size_t)(t0 + i) * HKV + hk) * DD + d0 + tx];
    __syncthreads();
    #pragma unroll
    for (int i = ty; i < 32; i += 8)
        VT[((size_t)hk * DD + d0 + i) * TT + t0 + tx] = tile[tx][i];
}

// ---------------- row RMS norm, fp16 output ----------------
__global__ void rms_rows_h(const float* __restrict__ X, const float* __restrict__ w,
                           __half* __restrict__ Y, int C) {
    int t = blockIdx.x;
    const float4* x4 = (const float4*)(X + (size_t)t * C);
    const float4* w4 = (const float4*)w;
    __half2*      y2 = (__half2*)(Y + (size_t)t * C);
    int n4 = C >> 2;
    float4 v[4];
    float ss = 0.f;
    int cnt = 0;
    for (int i = threadIdx.x; i < n4; i += 256) {
        float4 a = x4[i];
        v[cnt++] = a;
        ss += a.x * a.x + a.y * a.y + a.z * a.z + a.w * a.w;
    }
    #pragma unroll
    for (int o = 16; o; o >>= 1) ss += __shfl_xor_sync(0xffffffffu, ss, o);
    __shared__ float warpsum[8];
    if ((threadIdx.x & 31) == 0) warpsum[threadIdx.x >> 5] = ss;
    __syncthreads();
    ss = 0.f;
    #pragma unroll
    for (int i = 0; i < 8; i++) ss += warpsum[i];
    float r = rsqrtf(ss / (float)C + EPSF);
    cnt = 0;
    for (int i = threadIdx.x; i < n4; i += 256) {
        float4 a = v[cnt++];
        float4 ww = w4[i];
        y2[2 * i]     = __floats2half2_rn(a.x * r * ww.x, a.y * r * ww.y);
        y2[2 * i + 1] = __floats2half2_rn(a.z * r * ww.z, a.w * r * ww.w);
    }
}

// ---------------- per-head RMS + RoPE, fp16 in-place ----------------
__global__ void qk_rms_rope_h2(__half* __restrict__ buf, const float* __restrict__ w,
                               const float* __restrict__ cosT, const float* __restrict__ sinT,
                               float scale) {
    int h = blockIdx.x, t = blockIdx.y, nh = gridDim.x;
    __half* row = buf + ((size_t)t * nh + h) * DD;
    int d = threadIdx.x;
    float v = __half2float(row[d]);
    float ss = v * v;
    #pragma unroll
    for (int o = 16; o; o >>= 1) ss += __shfl_xor_sync(0xffffffffu, ss, o);
    __shared__ float wsum[4];
    if ((d & 31) == 0) wsum[d >> 5] = ss;
    __syncthreads();
    ss = wsum[0] + wsum[1] + wsum[2] + wsum[3];
    float r = rsqrtf(ss / 128.f + EPSF);
    float qn = v * r * w[d];
    __shared__ float sh[128];
    sh[d] = qn;
    __syncthreads();
    float rot = (d < 64) ? -sh[d + 64] : sh[d - 64];
    float val = (qn * cosT[(size_t)t * DD + d] + rot * sinT[(size_t)t * DD + d]) * scale;
    row[d] = __float2half(val);
}

#define MMA_F16(d, a, b)                                                      \
    asm volatile("mma.sync.aligned.m16n8k16.row.col.f32.f16.f16.f32 "         \
                 "{%0,%1,%2,%3}, {%4,%5,%6,%7}, {%8,%9}, {%0,%1,%2,%3};"      \
                 : "+f"(d[0]), "+f"(d[1]), "+f"(d[2]), "+f"(d[3])             \
                 : "r"(a[0]), "r"(a[1]), "r"(a[2]), "r"(a[3]),                \
                   "r"(b[0]), "r"(b[1]))

#define LDSM_X4(r0, r1, r2, r3, addr)                                         \
    asm volatile("ldmatrix.sync.aligned.m8n8.x4.shared.b16 {%0,%1,%2,%3}, [%4];" \
                 : "=r"(r0), "=r"(r1), "=r"(r2), "=r"(r3) : "r"(addr))

#define CP_ASYNC16(dst, src)                                                  \
    asm volatile("cp.async.cg.shared.global [%0], [%1], 16;\n"                \
                 :: "r"(dst), "l"(src))

// ---------------- fp16 tensor-core GEMM, cp.async 3-stage, BK=64, ldmatrix ---
// C[M,N] = A[M,K] * B[N,K]^T.
// MODE 0: +Res, fp32 out.  MODE 1: QKV routing, fp16 out.
// MODE 2: gate/up interleaved -> fused silu, fp16 out [M][N/2].
// MODE 3: +Res, fp32 out TRANSPOSED via smem staging ([N][T] layout).
#define HPITCH 72    // halfs per smem row (144 B): ldmatrix 8-row phase conflict-free
#define SMEM_F16 (3 * (128 + 128) * HPITCH * 2)   // 110592 B

template<int MODE>
__global__ __launch_bounds__(256, 2) void gemm_f16(
    const __half* __restrict__ A, const __half* __restrict__ B,
    const float* __restrict__ Res, float* __restrict__ C,
    __half* __restrict__ H0, __half* __restrict__ H1, __half* __restrict__ H2,
    int N, int K) {
    constexpr int BM = 128, BN = 128;
    extern __shared__ __half shm[];
    __half* SA = shm;                     // [3][BM][HPITCH]
    __half* SB = shm + 3 * BM * HPITCH;   // [3][BN][HPITCH]

    const int bm = blockIdx.y * BM;
    const int bn = blockIdx.x * BN;
    const int tid = threadIdx.x;
    const int wid = tid >> 5, lane = tid & 31;
    const int wm = wid & 1, wn = wid >> 1;
    const int lr = lane >> 2, lc = lane & 3;
    const int nkt = K >> 6;

    // ldmatrix lane-address components
    const int amat = lane >> 3;
    const int arow = ((amat & 1) << 3) + (lane & 7);
    const int acol = (amat >> 1) << 3;
    const int brow = ((amat >> 1) << 3) + (lane & 7);
    const int bcol = (amat & 1) << 3;
    const uint32_t sa0 = (uint32_t)__cvta_generic_to_shared(SA);
    const uint32_t sb0 = (uint32_t)__cvta_generic_to_shared(SB);
    const uint32_t a_off = sa0 + ((wm * 64 + arow) * HPITCH + acol) * 2;
    const uint32_t b_off = sb0 + ((wn * 32 + brow) * HPITCH + bcol) * 2;

    auto issue = [&](int kt, int s) {
        int k0 = kt << 6;
        #pragma unroll
        for (int i = 0; i < 4; i++) {
            int cid = tid + i * 256;
            int r = cid >> 3, ch = cid & 7;          // 8 x 16B chunks per 128B row
            const __half* g = A + (size_t)(bm + r) * K + k0 + ch * 8;
            uint32_t dst = (uint32_t)__cvta_generic_to_shared(
                &SA[(s * BM + r) * HPITCH + ch * 8]);
            CP_ASYNC16(dst, g);
        }
        #pragma unroll
        for (int i = 0; i < 4; i++) {
            int cid = tid + i * 256;
            int r = cid >> 3, ch = cid & 7;
            const __half* g = B + (size_t)(bn + r) * K + k0 + ch * 8;
            uint32_t dst = (uint32_t)__cvta_generic_to_shared(
                &SB[(s * BN + r) * HPITCH + ch * 8]);
            CP_ASYNC16(dst, g);
        }
        asm volatile("cp.async.commit_group;\n");
    };

    float acc[4][4][4] = {};

    issue(0, 0);
    issue(1, 1);

    for (int kt = 0; kt < nkt; kt++) {
        int s = kt % 3;
        if (kt == nkt - 1) { asm volatile("cp.async.wait_group 0;\n"); }
        else               { asm volatile("cp.async.wait_group 1;\n"); }
        __syncthreads();
        if (kt + 2 < nkt) issue(kt + 2, (kt + 2) % 3);

        uint32_t abase = a_off + s * (BM * HPITCH * 2);
        uint32_t bbase = b_off + s * (BN * HPITCH * 2);
        #pragma unroll
        for (int ks = 0; ks < 64; ks += 16) {
            uint32_t af[4][4], bf[4][2];
            #pragma unroll
            for (int mf = 0; mf < 4; mf++)
                LDSM_X4(af[mf][0], af[mf][1], af[mf][2], af[mf][3],
                        abase + (mf * 16 * HPITCH + ks) * 2);
            #pragma unroll
            for (int t = 0; t < 2; t++)
                LDSM_X4(bf[2 * t][0], bf[2 * t][1], bf[2 * t + 1][0], bf[2 * t + 1][1],
                        bbase + (t * 16 * HPITCH + ks) * 2);
            #pragma unroll
            for (int mf = 0; mf < 4; mf++)
                #pragma unroll
                for (int nf = 0; nf < 4; nf++)
                    MMA_F16(acc[mf][nf], af[mf], bf[nf]);
        }
    }

    if (MODE == 1) {
        // fp16 QKV routing
        __half* Cb;
        int Nloc, cl0;
        if (bn < 2048)      { Cb = H0; Nloc = 2048; cl0 = bn; }
        else if (bn < 3072) { Cb = H1; Nloc = 1024; cl0 = bn - 2048; }
        else                { Cb = H2; Nloc = 1024; cl0 = bn - 3072; }
        #pragma unroll
        for (int mf = 0; mf < 4; mf++) {
            #pragma unroll
            for (int nf = 0; nf < 4; nf++) {
                int rg = bm + wm * 64 + mf * 16 + lr;
                int cg = cl0 + wn * 32 + nf * 8 + 2 * lc;
                __half2 v0 = __floats2half2_rn(acc[mf][nf][0], acc[mf][nf][1]);
                __half2 v1 = __floats2half2_rn(acc[mf][nf][2], acc[mf][nf][3]);
                *(__half2*)(Cb + (size_t)rg * Nloc + cg) = v0;
                *(__half2*)(Cb + (size_t)(rg + 8) * Nloc + cg) = v1;
            }
        }
        return;
    }
    if (MODE == 2) {
        #pragma unroll
        for (int mf = 0; mf < 4; mf++) {
            #pragma unroll
            for (int nf = 0; nf < 4; nf++) {
                int rg = bm + wm * 64 + mf * 16 + lr;
                int j = ((bn + wn * 32 + nf * 8) >> 1) + lc;
                float g0 = acc[mf][nf][0], u0 = acc[mf][nf][1];
                float g1 = acc[mf][nf][2], u1 = acc[mf][nf][3];
                H0[(size_t)rg * (N / 2) + j] =
                    __float2half(g0 / (1.f + __expf(-g0)) * u0);
                H0[(size_t)(rg + 8) * (N / 2) + j] =
                    __float2half(g1 / (1.f + __expf(-g1)) * u1);
            }
        }
        return;
    }
    if (MODE == 3) {
        // residual add, stage through smem (pitch 132), coalesced transposed store
        __syncthreads();
        float* sf = (float*)shm;          // [128 cols][132] = 67584 B < SMEM_F16
        #pragma unroll
        for (int mf = 0; mf < 4; mf++) {
            #pragma unroll
            for (int nf = 0; nf < 4; nf++) {
                int rl = wm * 64 + mf * 16 + lr;
                int cl = wn * 32 + nf * 8 + 2 * lc;
                int rg = bm + rl;
                float2 r0 = *(const float2*)(Res + (size_t)rg * N + bn + cl);
                float2 r1 = *(const float2*)(Res + (size_t)(rg + 8) * N + bn + cl);
                sf[cl * 132 + rl]           = acc[mf][nf][0] + r0.x;
                sf[(cl + 1) * 132 + rl]     = acc[mf][nf][1] + r0.y;
                sf[cl * 132 + rl + 8]       = acc[mf][nf][2] + r1.x;
                sf[(cl + 1) * 132 + rl + 8] = acc[mf][nf][3] + r1.y;
            }
        }
        __syncthreads();
        #pragma unroll
        for (int i = 0; i < 16; i++) {
            int cl = wid * 16 + i;
            #pragma unroll
            for (int j = 0; j < 4; j++)
                C[(size_t)(bn + cl) * TT + bm + lane + 32 * j] =
                    sf[cl * 132 + lane + 32 * j];
        }
        return;
    }
    // MODE 0
    #pragma unroll
    for (int mf = 0; mf < 4; mf++) {
        #pragma unroll
        for (int nf = 0; nf < 4; nf++) {
            int rg = bm + wm * 64 + mf * 16 + lr;
            int cg = bn + wn * 32 + nf * 8 + 2 * lc;
            float2 v0 = make_float2(acc[mf][nf][0], acc[mf][nf][1]);
            float2 v1 = make_float2(acc[mf][nf][2], acc[mf][nf][3]);
            if (Res) {
                float2 r0 = *(const float2*)(Res + (size_t)rg * N + cg);
                float2 r1 = *(const float2*)(Res + (size_t)(rg + 8) * N + cg);
                v0.x += r0.x; v0.y += r0.y;
                v1.x += r1.x; v1.y += r1.y;
            }
            *(float2*)(C + (size_t)rg * N + cg) = v0;
            *(float2*)(C + (size_t)(rg + 8) * N + cg) = v1;
        }
    }
}

// ---------------- tensor-core flash attention, cp.async double-buffered K/V --
#define ATT_QP 136
#define ATT_KP 136
#define ATT_VP 72
#define ATT_SMEM ((128 * ATT_QP + 2 * (64 * ATT_KP + 128 * ATT_VP)) * 2)  // 106496 B

__global__ __launch_bounds__(256, 1) void flash_attn_h(
    const __half* __restrict__ Qh, const __half* __restrict__ Kh,
    const __half* __restrict__ VTh, __half* __restrict__ O) {
    extern __shared__ __half sma[];
    __half* Qs = sma;                          // [128][136]
    __half* Kb = Qs + 128 * ATT_QP;            // 2 x [64][136]
    __half* Vb = Kb + 2 * 64 * ATT_KP;         // 2 x [128][72]

    int h  = blockIdx.y;
    int it = gridDim.x - 1 - blockIdx.x;       // big tiles first
    int i0 = it * 128;
    int hk = h >> 1;                           // NREP = 2
    int tid = threadIdx.x, wid = tid >> 5, lane = tid & 31;
    int lr = lane >> 2, lc = lane & 3;
    int wrow = wid * 16;

    // K/V stage loader (cp.async)
    auto issue_att = [&](int kt, int s) {
        int j0 = kt * 64;
        __half* Kd = Kb + s * 64 * ATT_KP;
        __half* Vd = Vb + s * 128 * ATT_VP;
        #pragma unroll
        for (int i = 0; i < 4; i++) {
            int cid = tid + i * 256;
            int r = cid >> 4, ch = cid & 15;
            const __half* g = Kh + ((size_t)(j0 + r) * HKV + hk) * DD + ch * 8;
            uint32_t dst = (uint32_t)__cvta_generic_to_shared(&Kd[r * ATT_KP + ch * 8]);
            CP_ASYNC16(dst, g);
        }
        #pragma unroll
        for (int i = 0; i < 4; i++) {
            int cid = tid + i * 256;
            int d = cid >> 3, ch = cid & 7;
            const __half* g = VTh + ((size_t)hk * DD + d) * TT + j0 + ch * 8;
            uint32_t dst = (uint32_t)__cvta_generic_to_shared(&Vd[d * ATT_VP + ch * 8]);
            CP_ASYNC16(dst, g);
        }
        asm volatile("cp.async.commit_group;\n");
    };

    for (int idx = tid; idx < 2048; idx += 256) {
        int r = idx >> 4, ch = idx & 15;
        *(uint4*)&Qs[r * ATT_QP + ch * 8] =
            *(const uint4*)(Qh + ((size_t)(i0 + r) * HH + h) * DD + ch * 8);
    }

    float m_r0 = -1e30f, m_r1 = -1e30f, l_r0 = 0.f, l_r1 = 0.f;
    float oacc[16][4] = {};

    int nk = 2 * it + 2;
    issue_att(0, 0);

    for (int kt = 0; kt < nk; kt++) {
        asm volatile("cp.async.wait_group 0;\n");
        __syncthreads();                       // tile kt resident; buf kt-1 free
        if (kt + 1 < nk) issue_att(kt + 1, (kt + 1) & 1);
        const __half* Ks  = Kb + (kt & 1) * 64 * ATT_KP;
        const __half* VTs = Vb + (kt & 1) * 128 * ATT_VP;
        int j0 = kt * 64;

        float sacc[8][4] = {};
        #pragma unroll
        for (int ks = 0; ks < 8; ks++) {
            int k0 = ks * 16;
            uint32_t a[4];
            const __half* ap = Qs + (wrow + lr) * ATT_QP + k0 + 2 * lc;
            a[0] = *(const uint32_t*)(ap);
            a[1] = *(const uint32_t*)(ap + 8 * ATT_QP);
            a[2] = *(const uint32_t*)(ap + 8);
            a[3] = *(const uint32_t*)(ap + 8 * ATT_QP + 8);
            #pragma unroll
            for (int nf = 0; nf < 8; nf++) {
                uint32_t b[2];
                const __half* bp = Ks + (nf * 8 + lr) * ATT_KP + k0 + 2 * lc;
                b[0] = *(const uint32_t*)(bp);
                b[1] = *(const uint32_t*)(bp + 8);
                MMA_F16(sacc[nf], a, b);
            }
        }
        if (kt >= nk - 2) {
            int r0g = i0 + wrow + lr;
            #pragma unroll
            for (int nf = 0; nf < 8; nf++) {
                int col = j0 + nf * 8 + 2 * lc;
                if (col     > r0g)     sacc[nf][0] = -1e30f;
                if (col + 1 > r0g)     sacc[nf][1] = -1e30f;
                if (col     > r0g + 8) sacc[nf][2] = -1e30f;
                if (col + 1 > r0g + 8) sacc[nf][3] = -1e30f;
            }
        }
        float mx0 = m_r0, mx1 = m_r1;
        #pragma unroll
        for (int nf = 0; nf < 8; nf++) {
            mx0 = fmaxf(mx0, fmaxf(sacc[nf][0], sacc[nf][1]));
            mx1 = fmaxf(mx1, fmaxf(sacc[nf][2], sacc[nf][3]));
        }
        mx0 = fmaxf(mx0, __shfl_xor_sync(0xffffffffu, mx0, 1));
        mx0 = fmaxf(mx0, __shfl_xor_sync(0xffffffffu, mx0, 2));
        mx1 = fmaxf(mx1, __shfl_xor_sync(0xffffffffu, mx1, 1));
        mx1 = fmaxf(mx1, __shfl_xor_sync(0xffffffffu, mx1, 2));
        float al0 = __expf(m_r0 - mx0), al1 = __expf(m_r1 - mx1);
        m_r0 = mx0; m_r1 = mx1;
        float s0 = 0.f, s1 = 0.f;
        uint32_t pf[8][2];
        #pragma unroll
        for (int nf = 0; nf < 8; nf++) {
            float p0 = __expf(sacc[nf][0] - mx0);
            float p1 = __expf(sacc[nf][1] - mx0);
            float p2 = __expf(sacc[nf][2] - mx1);
            float p3 = __expf(sacc[nf][3] - mx1);
            s0 += p0 + p1; s1 += p2 + p3;
            __half2 h01 = __floats2half2_rn(p0, p1);
            __half2 h23 = __floats2half2_rn(p2, p3);
            pf[nf][0] = *(uint32_t*)&h01;
            pf[nf][1] = *(uint32_t*)&h23;
        }
        s0 += __shfl_xor_sync(0xffffffffu, s0, 1);
        s0 += __shfl_xor_sync(0xffffffffu, s0, 2);
        s1 += __shfl_xor_sync(0xffffffffu, s1, 1);
        s1 += __shfl_xor_sync(0xffffffffu, s1, 2);
        l_r0 = l_r0 * al0 + s0;
        l_r1 = l_r1 * al1 + s1;
        #pragma unroll
        for (int nf = 0; nf < 16; nf++) {
            oacc[nf][0] *= al0; oacc[nf][1] *= al0;
            oacc[nf][2] *= al1; oacc[nf][3] *= al1;
        }
        #pragma unroll
        for (int ks = 0; ks < 4; ks++) {
            uint32_t a[4] = { pf[2 * ks][0], pf[2 * ks][1],
                              pf[2 * ks + 1][0], pf[2 * ks + 1][1] };
            #pragma unroll
            for (int nf = 0; nf < 16; nf++) {
                uint32_t b[2];
                const __half* bp = VTs + (nf * 8 + lr) * ATT_VP + 16 * ks + 2 * lc;
                b[0] = *(const uint32_t*)(bp);
                b[1] = *(const uint32_t*)(bp + 8);
                MMA_F16(oacc[nf], a, b);
            }
        }
    }
    float inv0 = 1.f / l_r0, inv1 = 1.f / l_r1;
    #pragma unroll
    for (int nf = 0; nf < 16; nf++) {
        int d = nf * 8 + 2 * lc;
        __half2 o0 = __floats2half2_rn(oacc[nf][0] * inv0, oacc[nf][1] * inv0);
        __half2 o1 = __floats2half2_rn(oacc[nf][2] * inv1, oacc[nf][3] * inv1);
        *(uint32_t*)(O + ((size_t)(i0 + wrow + lr) * HH + h) * DD + d) = *(uint32_t*)&o0;
        *(uint32_t*)(O + ((size_t)(i0 + wrow + lr + 8) * HH + h) * DD + d) = *(uint32_t*)&o1;
    }
}

// ---------------- launch ----------------
extern "C" void kernel_launch(void* const* d_in, const int* in_sizes, int n_in,
                              void* d_out, int out_size) {
    const float* hc    = (const float*)d_in[0];
    const float* cosT  = (const float*)d_in[1];
    const float* sinT  = (const float*)d_in[2];
    const float* wq    = (const float*)d_in[5];
    const float* wk    = (const float*)d_in[6];
    const float* wv    = (const float*)d_in[7];
    const float* wo    = (const float*)d_in[8];
    const float* wgu   = (const float*)d_in[9];
    const float* wd    = (const float*)d_in[10];
    const float* ilnw  = (const float*)d_in[11];
    const float* plnw  = (const float*)d_in[12];
    const float* qnw   = (const float*)d_in[13];
    const float* knw   = (const float*)d_in[14];
    float* out = (float*)d_out;

    float *px, *phid;
    __half *phh, *patth, *ph2h, *pacth, *pqh, *pkh, *pvh, *pvth;
    __half *pwqkv, *pwo, *pwgu, *pwd;
    cudaGetSymbolAddress((void**)&px,    g_x);
    cudaGetSymbolAddress((void**)&phid,  g_hid);
    cudaGetSymbolAddress((void**)&phh,   g_h_h);
    cudaGetSymbolAddress((void**)&patth, g_att_h);
    cudaGetSymbolAddress((void**)&ph2h,  g_h2_h);
    cudaGetSymbolAddress((void**)&pacth, g_act_h);
    cudaGetSymbolAddress((void**)&pqh,   g_q_h);
    cudaGetSymbolAddress((void**)&pkh,   g_k_h);
    cudaGetSymbolAddress((void**)&pvh,   g_v_h);
    cudaGetSymbolAddress((void**)&pvth,  g_vt_h);
    cudaGetSymbolAddress((void**)&pwqkv, g_wqkv_h);
    cudaGetSymbolAddress((void**)&pwo,   g_wo_h);
    cudaGetSymbolAddress((void**)&pwgu,  g_wgu_h);
    cudaGetSymbolAddress((void**)&pwd,   g_wd_h);

    cudaFuncSetAttribute(flash_attn_h, cudaFuncAttributeMaxDynamicSharedMemorySize, ATT_SMEM);
    cudaFuncSetAttribute(gemm_f16<0>, cudaFuncAttributeMaxDynamicSharedMemorySize, SMEM_F16);
    cudaFuncSetAttribute(gemm_f16<1>, cudaFuncAttributeMaxDynamicSharedMemorySize, SMEM_F16);
    cudaFuncSetAttribute(gemm_f16<2>, cudaFuncAttributeMaxDynamicSharedMemorySize, SMEM_F16);
    cudaFuncSetAttribute(gemm_f16<3>, cudaFuncAttributeMaxDynamicSharedMemorySize, SMEM_F16);

    dim3 tb(32, 8);

    // 0. convert weights to fp16 (wgu with gate/up interleave)
    cvt_f16<<<(2048 * 2048 / 8) / 256, 256>>>((const float4*)wq,  (uint4*)pwqkv, 2048 * 2048 / 8);
    cvt_f16<<<(1024 * 2048 / 8) / 256, 256>>>((const float4*)wk,  (uint4*)(pwqkv + 2048 * 2048), 1024 * 2048 / 8);
    cvt_f16<<<(1024 * 2048 / 8) / 256, 256>>>((const float4*)wv,  (uint4*)(pwqkv + 3072 * 2048), 1024 * 2048 / 8);
    cvt_f16<<<(2048 * 2048 / 8) / 256, 256>>>((const float4*)wo,  (uint4*)pwo,  2048 * 2048 / 8);
    cvt_f16_gu<<<(16384 * 256) / 256, 256>>>((const float4*)wgu, (uint4*)pwgu);
    cvt_f16<<<(2048 * 8192 / 8) / 256, 256>>>((const float4*)wd,  (uint4*)pwd,  2048 * 8192 / 8);

    // 1. x = hidden_conv^T
    transpose_k<<<dim3(TT / 32, HID / 32), tb>>>(hc, px, HID, TT);
    // 2. h = rms(x) * input_ln_w -> fp16
    rms_rows_h<<<TT, 256>>>(px, ilnw, phh, HID);
    // 3. fused QKV projection -> fp16 q/k/v directly
    gemm_f16<1><<<dim3(32, 16), 256, SMEM_F16>>>(
        phh, pwqkv, nullptr, nullptr, pqh, pkh, pvh, 4096, HID);
    // 4. q/k head-RMS + rope in place (q pre-scaled); V transpose
    qk_rms_rope_h2<<<dim3(HH,  TT), 128>>>(pqh, qnw, cosT, sinT, SCALEF);
    qk_rms_rope_h2<<<dim3(HKV, TT), 128>>>(pkh, knw, cosT, sinT, 1.0f);
    v_trans_h2<<<dim3(TT / 32, DD / 32, HKV), tb>>>(pvh, pvth);
    // 5. tensor-core flash attention (cp.async K/V pipeline) -> fp16 att
    flash_attn_h<<<dim3(TT / 128, HH), 256, ATT_SMEM>>>(pqh, pkh, pvth, patth);
    // 6. hidden = x + att @ wo^T
    gemm_f16<0><<<dim3(16, 16), 256, SMEM_F16>>>(
        patth, pwo, px, phid, nullptr, nullptr, nullptr, HID, HH * DD);
    // 7. h2 = rms(hidden) * post_ln_w -> fp16
    rms_rows_h<<<TT, 256>>>(phid, plnw, ph2h, HID);
    // 8. gate_up with fused silu -> fp16 act
    gemm_f16<2><<<dim3(128, 16), 256, SMEM_F16>>>(
        ph2h, pwgu, nullptr, nullptr, pacth, nullptr, nullptr, 2 * II, HID);
    // 9. out = (hidden + act @ w_down^T)^T  (residual + staged transposed store)
    gemm_f16<3><<<dim3(16, 16), 256, SMEM_F16>>>(
        pacth, pwd, phid, out, nullptr, nullptr, nullptr, HID, II);
}